// round 5
// baseline (speedup 1.0000x reference)
#include <cuda_runtime.h>
#include <math.h>

#define BLOCK 128
#define NB 592
#define BJ 400
#define NBM (NB - BJ)
typedef unsigned long long u64;

__device__ float g_Ej[16000000];
__device__ float g_Em[8000000];
__device__ float g_pJ[BJ * 17], g_pM[NBM * 17];
__device__ float g_aV[NB]; __device__ int g_aI[NB]; __device__ float g_aS[NB];
__device__ float g_g1[16], g_g2[16], g_ejs[16];
__device__ float g_logpj; __device__ int g_selj;
__device__ int g_c0, g_c1, g_c2, g_c3;

__device__ __forceinline__ u64 F2(u64 a, u64 b, u64 c) {
    u64 r; asm("fma.rn.f32x2 %0,%1,%2,%3;" : "=l"(r) : "l"(a), "l"(b), "l"(c)); return r;
}
__device__ __forceinline__ u64 pack2(float lo, float hi) {
    u64 r; asm("mov.b64 %0,{%1,%2};" : "=l"(r) : "f"(lo), "f"(hi)); return r;
}
__device__ __forceinline__ float2 unpack2(u64 v) {
    float2 r; asm("mov.b64 {%0,%1},%2;" : "=f"(r.x), "=f"(r.y) : "l"(v)); return r;
}
__device__ __forceinline__ float ftanh(float x) {
    float e = __expf(2.0f * x);
    return __fdividef(e - 1.0f, e + 1.0f);
}

// 2-row 16x16 matvec on packed pairs: o[r][j] = b[j] + sum_d x[r][d]*W[j][d]
__device__ __forceinline__ void mv2(const u64* __restrict__ sW, const float* __restrict__ sb,
                                    const u64 (&x)[2][8], float (&o)[2][16]) {
#pragma unroll
    for (int j = 0; j < 16; j++) {
        u64 a0 = 0ull, a1 = 0ull;
#pragma unroll
        for (int d = 0; d < 8; d++) {
            u64 w = sW[j * 8 + d];
            a0 = F2(x[0][d], w, a0); a1 = F2(x[1][d], w, a1);
        }
        float b = sb[j]; float2 t;
        t = unpack2(a0); o[0][j] = t.x + t.y + b;
        t = unpack2(a1); o[1][j] = t.x + t.y + b;
    }
}
__device__ __forceinline__ void tp2(const float (&o)[2][16], u64 (&x)[2][8]) {
#pragma unroll
    for (int r = 0; r < 2; r++)
#pragma unroll
        for (int k = 0; k < 8; k++)
            x[r][k] = pack2(ftanh(o[r][2 * k]), ftanh(o[r][2 * k + 1]));
}
__device__ __forceinline__ void loadrow(const float* __restrict__ X, int row, u64 (&x)[8], bool ok) {
    if (ok) {
        const ulonglong2* p = (const ulonglong2*)(X + row * 16);
#pragma unroll
        for (int q = 0; q < 4; q++) { ulonglong2 u = p[q]; x[2 * q] = u.x; x[2 * q + 1] = u.y; }
    } else {
#pragma unroll
        for (int k = 0; k < 8; k++) x[k] = 0ull;
    }
}
__device__ __forceinline__ void redu17(float (&acc)[17], float* __restrict__ dst) {
#pragma unroll
    for (int k = 0; k < 17; k++)
#pragma unroll
        for (int o = 16; o > 0; o >>= 1) acc[k] += __shfl_down_sync(0xffffffffu, acc[k], o);
    __shared__ float red[4][17];
    int lane = threadIdx.x & 31, wid = threadIdx.x >> 5;
    if (lane == 0) {
#pragma unroll
        for (int k = 0; k < 17; k++) red[wid][k] = acc[k];
    }
    __syncthreads();
    if (threadIdx.x < 17) {
        float s = 0.f;
#pragma unroll
        for (int w = 0; w < 4; w++) s += red[w][threadIdx.x];
        dst[threadIdx.x] = s;
    }
}

// glimpse finalize (last block of a big pass): g = tanh(cat(q0,gJ,gM) @ W^T + b)
__device__ void fin_g(int t, const float* __restrict__ q0, const float* __restrict__ gW,
                      const float* __restrict__ gb, float* __restrict__ dst, int* cnt) {
    __shared__ float tA[7][17], tB[7][17], sA[17], sB[17], cat[48], sGW[768];
    int col = t % 17, grp = t / 17;
    if (grp < 7) {
        float a = 0.f, b = 0.f;
        for (int i = grp; i < BJ;  i += 7) a += g_pJ[i * 17 + col];
        for (int i = grp; i < NBM; i += 7) b += g_pM[i * 17 + col];
        tA[grp][col] = a; tB[grp][col] = b;
    }
    for (int i = t; i < 768; i += BLOCK) sGW[i] = gW[i];
    __syncthreads();
    if (t < 17) {
        float a = 0.f, b = 0.f;
#pragma unroll
        for (int g = 0; g < 7; g++) { a += tA[g][t]; b += tB[g][t]; }
        sA[t] = a; sB[t] = b;
    }
    __syncthreads();
    if (t < 16) {
        cat[t] = q0[t];
        cat[16 + t] = sA[1 + t] / sA[0];
        cat[32 + t] = sB[1 + t] / sB[0];
    }
    __syncthreads();
    if (t < 16) {
        float g = gb[t];
#pragma unroll
        for (int d = 0; d < 48; d++) g += cat[d] * sGW[t * 48 + d];
        dst[t] = tanhf(g);
    }
    if (t == 0) *cnt = 0;
}

// argmax finalize: which==0 -> sel_j/logpj/e_js ; which==1 -> write output
__device__ void fin_arg(int t, int which, float* __restrict__ out, int* cnt) {
    float bv = -3e38f, s = 0.f; int bi = 0x7fffffff;
    for (int i = t; i < NB; i += BLOCK) {
        float v = g_aV[i]; int ix = g_aI[i];
        if (v > bv || (v == bv && ix < bi)) { bv = v; bi = ix; }
        s += g_aS[i];
    }
#pragma unroll
    for (int o = 16; o > 0; o >>= 1) {
        float ov = __shfl_down_sync(0xffffffffu, bv, o);
        int   oi = __shfl_down_sync(0xffffffffu, bi, o);
        s += __shfl_down_sync(0xffffffffu, s, o);
        if (ov > bv || (ov == bv && oi < bi)) { bv = ov; bi = oi; }
    }
    __shared__ float wv[4], ws[4]; __shared__ int wi[4]; __shared__ int ssel;
    int lane = t & 31, wid = t >> 5;
    if (lane == 0) { wv[wid] = bv; wi[wid] = bi; ws[wid] = s; }
    __syncthreads();
    if (t == 0) {
        float v = wv[0]; int ix = wi[0]; float ss = ws[0];
#pragma unroll
        for (int w = 1; w < 4; w++) {
            if (wv[w] > v || (wv[w] == v && wi[w] < ix)) { v = wv[w]; ix = wi[w]; }
            ss += ws[w];
        }
        if (ix == 0x7fffffff) ix = 0;
        if (which == 0) { g_selj = ix; g_logpj = v - logf(ss); ssel = ix; }
        else { out[0] = (float)g_selj; out[1] = (float)ix; out[2] = g_logpj + (v - logf(ss)); }
        *cnt = 0;
    }
    __syncthreads();
    if (which == 0 && t < 16) g_ejs[t] = g_Ej[ssel * 16 + t];
}

// ---- pass 1: embed jobs+machines, glimpse-1 partials, fused g1 finalize ----
__global__ void __launch_bounds__(BLOCK, 4) k_emb(
    const float* __restrict__ jobs, const float* __restrict__ machs, int Nj, int Nm,
    const float* __restrict__ jW1, const float* __restrict__ jb1,
    const float* __restrict__ jW2, const float* __restrict__ jb2,
    const float* __restrict__ mW1, const float* __restrict__ mb1,
    const float* __restrict__ mW2, const float* __restrict__ mb2,
    const float* __restrict__ ajWr, const float* __restrict__ ajV,
    const float* __restrict__ ajWq, const float* __restrict__ ajbq,
    const float* __restrict__ amWr, const float* __restrict__ amV,
    const float* __restrict__ amWq, const float* __restrict__ ambq,
    const float* __restrict__ lastj, const float* __restrict__ g1W, const float* __restrict__ g1b)
{
    int t = threadIdx.x;
    int side = blockIdx.x >= BJ;
    int lb = side ? blockIdx.x - BJ : blockIdx.x;
    int nb = side ? NBM : BJ;
    const float* X = side ? machs : jobs;
    int N = side ? Nm : Nj;
    float* Eo = side ? g_Em : g_Ej;
    float* part = (side ? g_pM : g_pJ) + lb * 17;
    const float* W1 = side ? mW1 : jW1; const float* b1 = side ? mb1 : jb1;
    const float* W2 = side ? mW2 : jW2; const float* b2 = side ? mb2 : jb2;
    const float* Wr = side ? amWr : ajWr; const float* V = side ? amV : ajV;
    const float* Wq = side ? amWq : ajWq; const float* bq = side ? ambq : ajbq;

    __shared__ u64 sW1[128], sW2[128], sWr[128];
    __shared__ float sb1[16], sb2[16], sV[16], sQ[16];
    for (int i = t; i < 128; i += BLOCK) {
        sW1[i] = ((const u64*)W1)[i]; sW2[i] = ((const u64*)W2)[i]; sWr[i] = ((const u64*)Wr)[i];
    }
    if (t < 16) {
        sb1[t] = b1[t]; sb2[t] = b2[t]; sV[t] = V[t];
        float q = bq[t];
#pragma unroll
        for (int d = 0; d < 16; d++) q += lastj[d] * Wq[t * 16 + d];
        sQ[t] = q;
    }
    __syncthreads();

    float S = 0.f; u64 Wa[8];
#pragma unroll
    for (int k = 0; k < 8; k++) Wa[k] = 0ull;

    for (int base = lb * BLOCK * 2; base < N; base += nb * BLOCK * 2) {
        u64 x[2][8]; float o[2][16]; bool ok[2]; int rows[2];
#pragma unroll
        for (int r = 0; r < 2; r++) { rows[r] = base + t + r * BLOCK; ok[r] = rows[r] < N; loadrow(X, rows[r], x[r], ok[r]); }
        mv2(sW1, sb1, x, o); tp2(o, x);
        mv2(sW2, sb2, x, o); tp2(o, x);     // x = packed embeddings
#pragma unroll
        for (int r = 0; r < 2; r++) if (ok[r]) {
            ulonglong2* e = (ulonglong2*)(Eo + rows[r] * 16);
#pragma unroll
            for (int q = 0; q < 4; q++) { ulonglong2 u; u.x = x[r][2 * q]; u.y = x[r][2 * q + 1]; e[q] = u; }
        }
        mv2(sWr, sQ, x, o);                 // o = q' + E@Wr^T
#pragma unroll
        for (int r = 0; r < 2; r++) if (ok[r]) {
            float l = 0.f;
#pragma unroll
            for (int k = 0; k < 16; k++) l += sV[k] * ftanh(o[r][k]);
            float w = __expf(l); S += w;
            u64 wp = pack2(w, w);
#pragma unroll
            for (int k = 0; k < 8; k++) Wa[k] = F2(wp, x[r][k], Wa[k]);
        }
    }
    float acc[17]; acc[0] = S;
#pragma unroll
    for (int k = 0; k < 8; k++) { float2 u = unpack2(Wa[k]); acc[1 + 2 * k] = u.x; acc[2 + 2 * k] = u.y; }
    redu17(acc, part);
    __syncthreads();
    __shared__ int lastb;
    if (t == 0) { __threadfence(); lastb = (atomicAdd(&g_c0, 1) == NB - 1); }
    __syncthreads();
    if (lastb) fin_g(t, lastj, g1W, g1b, g_g1, &g_c0);
}

// ---- pass 3: glimpse-2 over stored embeddings, fused g2 finalize ----
__global__ void __launch_bounds__(BLOCK, 4) k_gl(
    int Nj, int Nm,
    const float* __restrict__ ajWr, const float* __restrict__ ajV,
    const float* __restrict__ ajWq, const float* __restrict__ ajbq,
    const float* __restrict__ amWr, const float* __restrict__ amV,
    const float* __restrict__ amWq, const float* __restrict__ ambq,
    const float* __restrict__ g2W, const float* __restrict__ g2b)
{
    int t = threadIdx.x;
    int side = blockIdx.x >= BJ;
    int lb = side ? blockIdx.x - BJ : blockIdx.x;
    int nb = side ? NBM : BJ;
    const float* X = side ? g_Em : g_Ej;
    int N = side ? Nm : Nj;
    float* part = (side ? g_pM : g_pJ) + lb * 17;
    const float* Wr = side ? amWr : ajWr; const float* V = side ? amV : ajV;
    const float* Wq = side ? amWq : ajWq; const float* bq = side ? ambq : ajbq;

    __shared__ u64 sWr[128];
    __shared__ float sV[16], sQ[16];
    for (int i = t; i < 128; i += BLOCK) sWr[i] = ((const u64*)Wr)[i];
    if (t < 16) {
        sV[t] = V[t];
        float q = bq[t];
#pragma unroll
        for (int d = 0; d < 16; d++) q += g_ejs[d] * Wq[t * 16 + d];
        sQ[t] = q;
    }
    __syncthreads();

    float S = 0.f; u64 Wa[8];
#pragma unroll
    for (int k = 0; k < 8; k++) Wa[k] = 0ull;

    for (int base = lb * BLOCK * 2; base < N; base += nb * BLOCK * 2) {
        u64 x[2][8]; float o[2][16]; bool ok[2];
#pragma unroll
        for (int r = 0; r < 2; r++) { int row = base + t + r * BLOCK; ok[r] = row < N; loadrow(X, row, x[r], ok[r]); }
        mv2(sWr, sQ, x, o);
#pragma unroll
        for (int r = 0; r < 2; r++) if (ok[r]) {
            float l = 0.f;
#pragma unroll
            for (int k = 0; k < 16; k++) l += sV[k] * ftanh(o[r][k]);
            float w = __expf(l); S += w;
            u64 wp = pack2(w, w);
#pragma unroll
            for (int k = 0; k < 8; k++) Wa[k] = F2(wp, x[r][k], Wa[k]);
        }
    }
    float acc[17]; acc[0] = S;
#pragma unroll
    for (int k = 0; k < 8; k++) { float2 u = unpack2(Wa[k]); acc[1 + 2 * k] = u.x; acc[2 + 2 * k] = u.y; }
    redu17(acc, part);
    __syncthreads();
    __shared__ int lastb;
    if (t == 0) { __threadfence(); lastb = (atomicAdd(&g_c2, 1) == NB - 1); }
    __syncthreads();
    if (lastb) fin_g(t, g_ejs, g2W, g2b, g_g2, &g_c2);
}

// ---- passes 2 & 4: pointer logits -> argmax + sumexp, fused finalize ----
__global__ void __launch_bounds__(BLOCK, 4) k_arg(
    int which, int N,
    const float* __restrict__ Wr, const float* __restrict__ V,
    const float* __restrict__ Wq, const float* __restrict__ bq,
    const void* __restrict__ maskp, int nmask, float* __restrict__ out)
{
    int t = threadIdx.x;
    const float* X = which ? g_Em : g_Ej;
    const float* qs = which ? g_g2 : g_g1;
    int* cnt = which ? &g_c3 : &g_c1;

    __shared__ u64 sWr[128];
    __shared__ float sV[16], sQ[16];
    __shared__ int smk;
    if (t == 0) smk = 0;
    for (int i = t; i < 128; i += BLOCK) sWr[i] = ((const u64*)Wr)[i];
    if (t < 16) {
        sV[t] = V[t];
        float q = bq[t];
#pragma unroll
        for (int d = 0; d < 16; d++) q += qs[d] * Wq[t * 16 + d];
        sQ[t] = q;
    }
    __syncthreads();
    // inline mask dtype detect: 0 = 4-byte elems (int32/float32), 1 = byte bools
    if (maskp) {
        int words = nmask >> 2; if (words > 4096) words = 4096;
        int f = 0;
        for (int i = t; i < words; i += BLOCK) {
            unsigned w = ((const unsigned*)maskp)[i];
            if (w != 0u && w != 1u && w != 0x3F800000u) f = 1;
        }
        if (f) atomicOr(&smk, 1);
    }
    __syncthreads();
    int mk = smk;

    float best = -3e38f, sum = 0.f; int bi = 0x7fffffff;
    for (int base = blockIdx.x * BLOCK * 2; base < N; base += NB * BLOCK * 2) {
        u64 x[2][8]; float o[2][16]; bool ok[2]; int rows[2];
#pragma unroll
        for (int r = 0; r < 2; r++) { rows[r] = base + t + r * BLOCK; ok[r] = rows[r] < N; loadrow(X, rows[r], x[r], ok[r]); }
        mv2(sWr, sQ, x, o);
#pragma unroll
        for (int r = 0; r < 2; r++) if (ok[r]) {
            bool pass = true;
            if (maskp) {
                if (mk) pass = ((const unsigned char*)maskp)[rows[r]] != 0;
                else    pass = ((const unsigned*)maskp)[rows[r]] != 0u;
            }
            if (pass) {
                float l = 0.f;
#pragma unroll
                for (int k = 0; k < 16; k++) l += sV[k] * ftanh(o[r][k]);
                sum += __expf(l);
                if (l > best) { best = l; bi = rows[r]; }
            }
        }
    }
#pragma unroll
    for (int of = 16; of > 0; of >>= 1) {
        float ov = __shfl_down_sync(0xffffffffu, best, of);
        int   oi = __shfl_down_sync(0xffffffffu, bi, of);
        sum += __shfl_down_sync(0xffffffffu, sum, of);
        if (ov > best || (ov == best && oi < bi)) { best = ov; bi = oi; }
    }
    __shared__ float wv[4], ws[4]; __shared__ int wi[4];
    int lane = t & 31, wid = t >> 5;
    if (lane == 0) { wv[wid] = best; wi[wid] = bi; ws[wid] = sum; }
    __syncthreads();
    if (t == 0) {
        float v = wv[0]; int ix = wi[0]; float s = ws[0];
#pragma unroll
        for (int w = 1; w < 4; w++) {
            if (wv[w] > v || (wv[w] == v && wi[w] < ix)) { v = wv[w]; ix = wi[w]; }
            s += ws[w];
        }
        g_aV[blockIdx.x] = v; g_aI[blockIdx.x] = ix; g_aS[blockIdx.x] = s;
    }
    __syncthreads();
    __shared__ int lastb;
    if (t == 0) { __threadfence(); lastb = (atomicAdd(cnt, 1) == NB - 1); }
    __syncthreads();
    if (lastb) fin_arg(t, which, out, cnt);
}

extern "C" void kernel_launch(void* const* d_in, const int* in_sizes, int n_in,
                              void* d_out, int out_size) {
    const float* jobs  = (const float*)d_in[0];
    const float* machs = (const float*)d_in[1];
    const void*  mask  = d_in[2];
    const float *jW1=(const float*)d_in[3], *jb1=(const float*)d_in[4], *jW2=(const float*)d_in[5], *jb2=(const float*)d_in[6];
    const float *mW1=(const float*)d_in[7], *mb1=(const float*)d_in[8], *mW2=(const float*)d_in[9], *mb2=(const float*)d_in[10];
    const float *ajWq=(const float*)d_in[11], *ajbq=(const float*)d_in[12], *ajWr=(const float*)d_in[13], *ajV=(const float*)d_in[14];
    const float *amWq=(const float*)d_in[15], *ambq=(const float*)d_in[16], *amWr=(const float*)d_in[17], *amV=(const float*)d_in[18];
    const float *jaWq=(const float*)d_in[19], *jabq=(const float*)d_in[20], *jaWr=(const float*)d_in[21], *jaV=(const float*)d_in[22];
    const float *maWq=(const float*)d_in[23], *mabq=(const float*)d_in[24], *maWr=(const float*)d_in[25], *maV=(const float*)d_in[26];
    const float *g1W=(const float*)d_in[27], *g1b=(const float*)d_in[28];
    const float *g2W=(const float*)d_in[29], *g2b=(const float*)d_in[30];
    const float *lastj=(const float*)d_in[31];
    int Nj = in_sizes[0] / 16;
    int Nm = in_sizes[1] / 16;
    float* out = (float*)d_out;

    k_emb<<<NB, BLOCK>>>(jobs, machs, Nj, Nm, jW1, jb1, jW2, jb2, mW1, mb1, mW2, mb2,
                         ajWr, ajV, ajWq, ajbq, amWr, amV, amWq, ambq, lastj, g1W, g1b);
    k_arg<<<NB, BLOCK>>>(0, Nj, jaWr, jaV, jaWq, jabq, mask, in_sizes[2], out);
    k_gl <<<NB, BLOCK>>>(Nj, Nm, ajWr, ajV, ajWq, ajbq, amWr, amV, amWq, ambq, g2W, g2b);
    k_arg<<<NB, BLOCK>>>(1, Nm, maWr, maV, maWq, mabq, nullptr, 0, out);
    (void)n_in; (void)out_size;
}

// round 6
// speedup vs baseline: 1.1746x; 1.1746x over previous
#include <cuda_runtime.h>
#include <math.h>

#define BLOCK 128
#define NB 592
#define BJ 400
#define NBM (NB - BJ)
typedef unsigned long long u64;

__device__ float g_Ej[16000000];
__device__ float g_Em[8000000];
__device__ float g_pJ[BJ * 17], g_pM[NBM * 17];
__device__ float g_aV[NB]; __device__ int g_aI[NB]; __device__ float g_aS[NB];
__device__ float g_g1[16], g_g2[16], g_ejs[16];
__device__ float g_logpj; __device__ int g_selj;
__device__ int g_c0, g_c1, g_c2, g_c3;

// ---------- packed f32x2 helpers ----------
__device__ __forceinline__ u64 F2(u64 a, u64 b, u64 c) {
    u64 r; asm("fma.rn.f32x2 %0,%1,%2,%3;" : "=l"(r) : "l"(a), "l"(b), "l"(c)); return r;
}
__device__ __forceinline__ u64 pack2(float lo, float hi) {
    u64 r; asm("mov.b64 %0,{%1,%2};" : "=l"(r) : "f"(lo), "f"(hi)); return r;
}
__device__ __forceinline__ float2 unpack2(u64 v) {
    float2 r; asm("mov.b64 {%0,%1},%2;" : "=f"(r.x), "=f"(r.y) : "l"(v)); return r;
}
__device__ __forceinline__ float ftanh(float x) {
    float e = __expf(2.0f * x);
    return __fdividef(e - 1.0f, e + 1.0f);
}

// ---------- bulk-async + mbarrier primitives ----------
__device__ __forceinline__ unsigned s2u(const void* p) {
    return (unsigned)__cvta_generic_to_shared(p);
}
__device__ __forceinline__ void mb_init(unsigned a, unsigned c) {
    asm volatile("mbarrier.init.shared.b64 [%0], %1;" :: "r"(a), "r"(c) : "memory");
}
__device__ __forceinline__ void mb_tx(unsigned a, unsigned bytes) {
    asm volatile("mbarrier.arrive.expect_tx.shared.b64 _, [%0], %1;" :: "r"(a), "r"(bytes) : "memory");
}
__device__ __forceinline__ void mb_wait(unsigned a, unsigned p) {
    asm volatile(
        "{\n\t.reg .pred P;\n"
        "WL%=:\n\t"
        "mbarrier.try_wait.parity.acquire.cta.shared::cta.b64 P, [%0], %1, 0x989680;\n\t"
        "@P bra WD%=;\n\t"
        "bra WL%=;\n"
        "WD%=:\n\t}"
        :: "r"(a), "r"(p) : "memory");
}
__device__ __forceinline__ void bulk_g2s(unsigned dst, const void* src, unsigned sz, unsigned mb) {
    asm volatile("cp.async.bulk.shared::cluster.global.mbarrier::complete_tx::bytes [%0], [%1], %2, [%3];"
                 :: "r"(dst), "l"(src), "r"(sz), "r"(mb) : "memory");
}
__device__ __forceinline__ void bulk_s2g(void* dst, unsigned src, unsigned sz) {
    asm volatile("cp.async.bulk.global.shared::cta.bulk_group [%0], [%1], %2;"
                 :: "l"(dst), "r"(src), "r"(sz) : "memory");
}
__device__ __forceinline__ void bulk_commit() { asm volatile("cp.async.bulk.commit_group;" ::: "memory"); }
__device__ __forceinline__ void bulk_wait1() { asm volatile("cp.async.bulk.wait_group 1;" ::: "memory"); }
__device__ __forceinline__ void bulk_wait0() { asm volatile("cp.async.bulk.wait_group 0;" ::: "memory"); }
__device__ __forceinline__ void fence_async() { asm volatile("fence.proxy.async.shared::cta;" ::: "memory"); }

// rotated-quarter LDS/STS of one 64B row (cuts 64B-stride bank conflicts)
__device__ __forceinline__ void lds_row(unsigned sbase, int lr, u64 (&x)[8]) {
#pragma unroll
    for (int i = 0; i < 4; i++) {
        int q = (i + lr) & 3; u64 a, b;
        asm volatile("ld.shared.v2.b64 {%0,%1},[%2];" : "=l"(a), "=l"(b) : "r"(sbase + lr * 64 + q * 16));
        x[2 * q] = a; x[2 * q + 1] = b;
    }
}
__device__ __forceinline__ void sts_row(unsigned sbase, int lr, const u64 (&x)[8]) {
#pragma unroll
    for (int i = 0; i < 4; i++) {
        int q = (i + lr) & 3;
        asm volatile("st.shared.v2.b64 [%0],{%1,%2};" :: "r"(sbase + lr * 64 + q * 16),
                     "l"(x[2 * q]), "l"(x[2 * q + 1]) : "memory");
    }
}

// single-row 16x16 matvec on packed pairs
__device__ __forceinline__ void mv1(const u64* __restrict__ sW, const float* __restrict__ sb_,
                                    const u64 (&x)[8], float (&o)[16]) {
#pragma unroll
    for (int j = 0; j < 16; j++) {
        u64 a = 0ull;
#pragma unroll
        for (int d = 0; d < 8; d++) a = F2(x[d], sW[j * 8 + d], a);
        float2 t = unpack2(a); o[j] = t.x + t.y + sb_[j];
    }
}
// two-row version
__device__ __forceinline__ void mv2(const u64* __restrict__ sW, const float* __restrict__ sb_,
                                    const u64 (&x)[2][8], float (&o)[2][16]) {
#pragma unroll
    for (int j = 0; j < 16; j++) {
        u64 a0 = 0ull, a1 = 0ull;
#pragma unroll
        for (int d = 0; d < 8; d++) {
            u64 w = sW[j * 8 + d];
            a0 = F2(x[0][d], w, a0); a1 = F2(x[1][d], w, a1);
        }
        float b = sb_[j]; float2 t;
        t = unpack2(a0); o[0][j] = t.x + t.y + b;
        t = unpack2(a1); o[1][j] = t.x + t.y + b;
    }
}

__device__ __forceinline__ void redu17(float (&acc)[17], float* __restrict__ dst) {
#pragma unroll
    for (int k = 0; k < 17; k++)
#pragma unroll
        for (int o = 16; o > 0; o >>= 1) acc[k] += __shfl_down_sync(0xffffffffu, acc[k], o);
    __shared__ float red[4][17];
    int lane = threadIdx.x & 31, wid = threadIdx.x >> 5;
    if (lane == 0) {
#pragma unroll
        for (int k = 0; k < 17; k++) red[wid][k] = acc[k];
    }
    __syncthreads();
    if (threadIdx.x < 17) {
        float s = 0.f;
#pragma unroll
        for (int w = 0; w < 4; w++) s += red[w][threadIdx.x];
        dst[threadIdx.x] = s;
    }
}

// glimpse finalize (last block): g = tanh(cat(q0,gJ,gM) @ W^T + b)
__device__ void fin_g(int t, const float* __restrict__ q0, const float* __restrict__ gW,
                      const float* __restrict__ gb, float* __restrict__ dst, int* cnt) {
    __shared__ float tA[7][17], tB[7][17], sA[17], sB[17], cat[48], sGW[768];
    int col = t % 17, grp = t / 17;
    if (grp < 7) {
        float a = 0.f, b = 0.f;
        for (int i = grp; i < BJ;  i += 7) a += g_pJ[i * 17 + col];
        for (int i = grp; i < NBM; i += 7) b += g_pM[i * 17 + col];
        tA[grp][col] = a; tB[grp][col] = b;
    }
    for (int i = t; i < 768; i += BLOCK) sGW[i] = gW[i];
    __syncthreads();
    if (t < 17) {
        float a = 0.f, b = 0.f;
#pragma unroll
        for (int g = 0; g < 7; g++) { a += tA[g][t]; b += tB[g][t]; }
        sA[t] = a; sB[t] = b;
    }
    __syncthreads();
    if (t < 16) {
        cat[t] = q0[t];
        cat[16 + t] = sA[1 + t] / sA[0];
        cat[32 + t] = sB[1 + t] / sB[0];
    }
    __syncthreads();
    if (t < 16) {
        float g = gb[t];
#pragma unroll
        for (int d = 0; d < 48; d++) g += cat[d] * sGW[t * 48 + d];
        dst[t] = tanhf(g);
    }
    if (t == 0) *cnt = 0;
}

// argmax finalize
__device__ void fin_arg(int t, int which, float* __restrict__ out, int* cnt) {
    float bv = -3e38f, s = 0.f; int bi = 0x7fffffff;
    for (int i = t; i < NB; i += BLOCK) {
        float v = g_aV[i]; int ix = g_aI[i];
        if (v > bv || (v == bv && ix < bi)) { bv = v; bi = ix; }
        s += g_aS[i];
    }
#pragma unroll
    for (int o = 16; o > 0; o >>= 1) {
        float ov = __shfl_down_sync(0xffffffffu, bv, o);
        int   oi = __shfl_down_sync(0xffffffffu, bi, o);
        s += __shfl_down_sync(0xffffffffu, s, o);
        if (ov > bv || (ov == bv && oi < bi)) { bv = ov; bi = oi; }
    }
    __shared__ float wv[4], ws[4]; __shared__ int wi[4]; __shared__ int ssel;
    int lane = t & 31, wid = t >> 5;
    if (lane == 0) { wv[wid] = bv; wi[wid] = bi; ws[wid] = s; }
    __syncthreads();
    if (t == 0) {
        float v = wv[0]; int ix = wi[0]; float ss = ws[0];
#pragma unroll
        for (int w = 1; w < 4; w++) {
            if (wv[w] > v || (wv[w] == v && wi[w] < ix)) { v = wv[w]; ix = wi[w]; }
            ss += ws[w];
        }
        if (ix == 0x7fffffff) ix = 0;
        if (which == 0) { g_selj = ix; g_logpj = v - logf(ss); ssel = ix; }
        else { out[0] = (float)g_selj; out[1] = (float)ix; out[2] = g_logpj + (v - logf(ss)); }
        *cnt = 0;
    }
    __syncthreads();
    if (which == 0 && t < 16) g_ejs[t] = g_Ej[ssel * 16 + t];
}

// ================= pass 1: embed + glimpse-1, bulk in/out pipeline =================
#define CH1 128
#define CB1 (CH1 * 64)
#define NS1 4
__global__ void __launch_bounds__(BLOCK, 4) k_emb(
    const float* __restrict__ jobs, const float* __restrict__ machs, int Nj, int Nm,
    const float* __restrict__ jW1, const float* __restrict__ jb1,
    const float* __restrict__ jW2, const float* __restrict__ jb2,
    const float* __restrict__ mW1, const float* __restrict__ mb1,
    const float* __restrict__ mW2, const float* __restrict__ mb2,
    const float* __restrict__ ajWr, const float* __restrict__ ajV,
    const float* __restrict__ ajWq, const float* __restrict__ ajbq,
    const float* __restrict__ amWr, const float* __restrict__ amV,
    const float* __restrict__ amWq, const float* __restrict__ ambq,
    const float* __restrict__ lastj, const float* __restrict__ g1W, const float* __restrict__ g1b)
{
    __shared__ __align__(128) char inb[NS1][CB1];
    __shared__ __align__(128) char outb[2][CB1];
    __shared__ u64 mbs[NS1];
    __shared__ u64 sW1[128], sW2[128], sWr[128];
    __shared__ float sb1[16], sb2[16], sV[16], sQ[16];

    int t = threadIdx.x;
    int side = blockIdx.x >= BJ;
    int lb = side ? blockIdx.x - BJ : blockIdx.x;
    int nb = side ? NBM : BJ;
    const float* X = side ? machs : jobs;
    int N = side ? Nm : Nj;
    float* Eo = side ? g_Em : g_Ej;
    float* part = (side ? g_pM : g_pJ) + lb * 17;
    const float* W1 = side ? mW1 : jW1; const float* b1 = side ? mb1 : jb1;
    const float* W2 = side ? mW2 : jW2; const float* b2 = side ? mb2 : jb2;
    const float* Wr = side ? amWr : ajWr; const float* V = side ? amV : ajV;
    const float* Wq = side ? amWq : ajWq; const float* bq = side ? ambq : ajbq;

    for (int i = t; i < 128; i += BLOCK) {
        sW1[i] = ((const u64*)W1)[i]; sW2[i] = ((const u64*)W2)[i]; sWr[i] = ((const u64*)Wr)[i];
    }
    if (t < 16) {
        sb1[t] = b1[t]; sb2[t] = b2[t]; sV[t] = V[t];
        float q = bq[t];
#pragma unroll
        for (int d = 0; d < 16; d++) q += lastj[d] * Wq[t * 16 + d];
        sQ[t] = q;
    }
    if (t == 0)
        for (int s = 0; s < NS1; s++) mb_init(s2u(&mbs[s]), 1);
    __syncthreads();

    int nch = (N + CH1 - 1) / CH1;
    if (t == 0) {
#pragma unroll
        for (int s = 0; s < NS1; s++) {
            int c = lb + s * nb;
            if (c < nch) {
                int rows = N - c * CH1; if (rows > CH1) rows = CH1;
                mb_tx(s2u(&mbs[s]), rows * 64);
                bulk_g2s(s2u(&inb[s][0]), (const void*)(X + (size_t)c * CH1 * 16), rows * 64, s2u(&mbs[s]));
            }
        }
    }

    float S = 0.f; u64 Wa[8];
#pragma unroll
    for (int k = 0; k < 8; k++) Wa[k] = 0ull;

    for (int k = 0; ; k++) {
        int c = lb + k * nb;
        if (c >= nch) break;
        int s = k % NS1; unsigned ph = (unsigned)((k / NS1) & 1);
        mb_wait(s2u(&mbs[s]), ph);

        int row0 = c * CH1;
        int rows = N - row0; if (rows > CH1) rows = CH1;
        bool ok = t < rows;
        u64 x[8]; float o[16];
        if (ok) lds_row(s2u(&inb[s][0]), t, x);
        else { for (int i = 0; i < 8; i++) x[i] = 0ull; }

        mv1(sW1, sb1, x, o);
#pragma unroll
        for (int i = 0; i < 8; i++) x[i] = pack2(ftanh(o[2 * i]), ftanh(o[2 * i + 1]));
        mv1(sW2, sb2, x, o);
#pragma unroll
        for (int i = 0; i < 8; i++) x[i] = pack2(ftanh(o[2 * i]), ftanh(o[2 * i + 1]));   // x = emb

        int os = k & 1;
        if (k >= 2 && t == 0) bulk_wait1();      // outb[os] free (store k-2 done)
        __syncthreads();
        if (ok) sts_row(s2u(&outb[os][0]), t, x);
        fence_async();

        if (ok) {                                 // glimpse-1 accumulation
            mv1(sWr, sQ, x, o);
            float l = 0.f;
#pragma unroll
            for (int kk = 0; kk < 16; kk++) l += sV[kk] * ftanh(o[kk]);
            float w = __expf(l); S += w;
            u64 wp = pack2(w, w);
#pragma unroll
            for (int kk = 0; kk < 8; kk++) Wa[kk] = F2(wp, x[kk], Wa[kk]);
        }
        __syncthreads();
        if (t == 0) {
            bulk_s2g((void*)(Eo + (size_t)row0 * 16), s2u(&outb[os][0]), rows * 64);
            bulk_commit();
            int cn = lb + (k + NS1) * nb;
            if (cn < nch) {
                int rn = N - cn * CH1; if (rn > CH1) rn = CH1;
                mb_tx(s2u(&mbs[s]), rn * 64);
                bulk_g2s(s2u(&inb[s][0]), (const void*)(X + (size_t)cn * CH1 * 16), rn * 64, s2u(&mbs[s]));
            }
        }
    }
    if (t == 0) bulk_wait0();

    float acc[17]; acc[0] = S;
#pragma unroll
    for (int k = 0; k < 8; k++) { float2 u = unpack2(Wa[k]); acc[1 + 2 * k] = u.x; acc[2 + 2 * k] = u.y; }
    redu17(acc, part);
    __syncthreads();
    __shared__ int lastb;
    if (t == 0) { __threadfence(); lastb = (atomicAdd(&g_c0, 1) == NB - 1); }
    __syncthreads();
    if (lastb) fin_g(t, lastj, g1W, g1b, g_g1, &g_c0);
}

// ================= pass 3: glimpse-2 over stored E, bulk pipeline =================
#define CH2 256
#define CB2 (CH2 * 64)
#define NS2 3
__global__ void __launch_bounds__(BLOCK, 4) k_gl(
    int Nj, int Nm,
    const float* __restrict__ ajWr, const float* __restrict__ ajV,
    const float* __restrict__ ajWq, const float* __restrict__ ajbq,
    const float* __restrict__ amWr, const float* __restrict__ amV,
    const float* __restrict__ amWq, const float* __restrict__ ambq,
    const float* __restrict__ g2W, const float* __restrict__ g2b)
{
    __shared__ __align__(128) char inb[NS2][CB2];
    __shared__ u64 mbs[NS2];
    __shared__ u64 sWr[128];
    __shared__ float sV[16], sQ[16];

    int t = threadIdx.x;
    int side = blockIdx.x >= BJ;
    int lb = side ? blockIdx.x - BJ : blockIdx.x;
    int nb = side ? NBM : BJ;
    const float* X = side ? g_Em : g_Ej;
    int N = side ? Nm : Nj;
    float* part = (side ? g_pM : g_pJ) + lb * 17;
    const float* Wr = side ? amWr : ajWr; const float* V = side ? amV : ajV;
    const float* Wq = side ? amWq : ajWq; const float* bq = side ? ambq : ajbq;

    for (int i = t; i < 128; i += BLOCK) sWr[i] = ((const u64*)Wr)[i];
    if (t < 16) {
        sV[t] = V[t];
        float q = bq[t];
#pragma unroll
        for (int d = 0; d < 16; d++) q += g_ejs[d] * Wq[t * 16 + d];
        sQ[t] = q;
    }
    if (t == 0)
        for (int s = 0; s < NS2; s++) mb_init(s2u(&mbs[s]), 1);
    __syncthreads();

    int nch = (N + CH2 - 1) / CH2;
    if (t == 0) {
#pragma unroll
        for (int s = 0; s < NS2; s++) {
            int c = lb + s * nb;
            if (c < nch) {
                int rows = N - c * CH2; if (rows > CH2) rows = CH2;
                mb_tx(s2u(&mbs[s]), rows * 64);
                bulk_g2s(s2u(&inb[s][0]), (const void*)(X + (size_t)c * CH2 * 16), rows * 64, s2u(&mbs[s]));
            }
        }
    }

    float S = 0.f; u64 Wa[8];
#pragma unroll
    for (int k = 0; k < 8; k++) Wa[k] = 0ull;

    for (int k = 0; ; k++) {
        int c = lb + k * nb;
        if (c >= nch) break;
        int s = k % NS2; unsigned ph = (unsigned)((k / NS2) & 1);
        mb_wait(s2u(&mbs[s]), ph);

        int row0 = c * CH2;
        int rows = N - row0; if (rows > CH2) rows = CH2;
        u64 x[2][8]; float o[2][16]; bool ok[2]; int lr[2];
        lr[0] = t; lr[1] = t + BLOCK;
#pragma unroll
        for (int r = 0; r < 2; r++) {
            ok[r] = lr[r] < rows;
            if (ok[r]) lds_row(s2u(&inb[s][0]), lr[r], x[r]);
            else { for (int i = 0; i < 8; i++) x[r][i] = 0ull; }
        }
        mv2(sWr, sQ, x, o);
#pragma unroll
        for (int r = 0; r < 2; r++) if (ok[r]) {
            float l = 0.f;
#pragma unroll
            for (int kk = 0; kk < 16; kk++) l += sV[kk] * ftanh(o[r][kk]);
            float w = __expf(l); S += w;
            u64 wp = pack2(w, w);
#pragma unroll
            for (int kk = 0; kk < 8; kk++) Wa[kk] = F2(wp, x[r][kk], Wa[kk]);
        }
        __syncthreads();
        if (t == 0) {
            int cn = lb + (k + NS2) * nb;
            if (cn < nch) {
                int rn = N - cn * CH2; if (rn > CH2) rn = CH2;
                mb_tx(s2u(&mbs[s]), rn * 64);
                bulk_g2s(s2u(&inb[s][0]), (const void*)(X + (size_t)cn * CH2 * 16), rn * 64, s2u(&mbs[s]));
            }
        }
    }

    float acc[17]; acc[0] = S;
#pragma unroll
    for (int k = 0; k < 8; k++) { float2 u = unpack2(Wa[k]); acc[1 + 2 * k] = u.x; acc[2 + 2 * k] = u.y; }
    redu17(acc, part);
    __syncthreads();
    __shared__ int lastb;
    if (t == 0) { __threadfence(); lastb = (atomicAdd(&g_c2, 1) == NB - 1); }
    __syncthreads();
    if (lastb) fin_g(t, g_ejs, g2W, g2b, g_g2, &g_c2);
}

// ================= passes 2 & 4: pointer logits -> argmax + sumexp =================
__global__ void __launch_bounds__(BLOCK, 4) k_arg(
    int which, int N,
    const float* __restrict__ Wr, const float* __restrict__ V,
    const float* __restrict__ Wq, const float* __restrict__ bq,
    const void* __restrict__ maskp, int nmask, float* __restrict__ out)
{
    __shared__ __align__(128) char inb[NS2][CB2];
    __shared__ u64 mbs[NS2];
    __shared__ u64 sWr[128];
    __shared__ float sV[16], sQ[16];
    __shared__ int smk;

    int t = threadIdx.x;
    const float* X = which ? g_Em : g_Ej;
    const float* qs = which ? g_g2 : g_g1;
    int* cnt = which ? &g_c3 : &g_c1;

    if (t == 0) smk = 0;
    for (int i = t; i < 128; i += BLOCK) sWr[i] = ((const u64*)Wr)[i];
    if (t < 16) {
        sV[t] = V[t];
        float q = bq[t];
#pragma unroll
        for (int d = 0; d < 16; d++) q += qs[d] * Wq[t * 16 + d];
        sQ[t] = q;
    }
    if (t == 0)
        for (int s = 0; s < NS2; s++) mb_init(s2u(&mbs[s]), 1);
    __syncthreads();
    // mask dtype detect: 0 = 4-byte elems (int32/float32), 1 = byte bools
    if (maskp) {
        int words = nmask >> 2; if (words > 4096) words = 4096;
        int f = 0;
        for (int i = t; i < words; i += BLOCK) {
            unsigned w = ((const unsigned*)maskp)[i];
            if (w != 0u && w != 1u && w != 0x3F800000u) f = 1;
        }
        if (f) atomicOr(&smk, 1);
    }
    __syncthreads();
    int mk = smk;

    int nch = (N + CH2 - 1) / CH2;
    if (t == 0) {
#pragma unroll
        for (int s = 0; s < NS2; s++) {
            int c = blockIdx.x + s * NB;
            if (c < nch) {
                int rows = N - c * CH2; if (rows > CH2) rows = CH2;
                mb_tx(s2u(&mbs[s]), rows * 64);
                bulk_g2s(s2u(&inb[s][0]), (const void*)(X + (size_t)c * CH2 * 16), rows * 64, s2u(&mbs[s]));
            }
        }
    }

    float best = -3e38f, sum = 0.f; int bi = 0x7fffffff;
    for (int k = 0; ; k++) {
        int c = blockIdx.x + k * NB;
        if (c >= nch) break;
        int s = k % NS2; unsigned ph = (unsigned)((k / NS2) & 1);
        mb_wait(s2u(&mbs[s]), ph);

        int row0 = c * CH2;
        int rows = N - row0; if (rows > CH2) rows = CH2;
        u64 x[2][8]; float o[2][16]; bool ok[2]; int lr[2];
        lr[0] = t; lr[1] = t + BLOCK;
#pragma unroll
        for (int r = 0; r < 2; r++) {
            ok[r] = lr[r] < rows;
            if (ok[r]) lds_row(s2u(&inb[s][0]), lr[r], x[r]);
            else { for (int i = 0; i < 8; i++) x[r][i] = 0ull; }
        }
        mv2(sWr, sQ, x, o);
#pragma unroll
        for (int r = 0; r < 2; r++) if (ok[r]) {
            int row = row0 + lr[r];
            bool pass = true;
            if (maskp) {
                if (mk) pass = ((const unsigned char*)maskp)[row] != 0;
                else    pass = ((const unsigned*)maskp)[row] != 0u;
            }
            if (pass) {
                float l = 0.f;
#pragma unroll
                for (int kk = 0; kk < 16; kk++) l += sV[kk] * ftanh(o[r][kk]);
                sum += __expf(l);
                if (l > best) { best = l; bi = row; }
            }
        }
        __syncthreads();
        if (t == 0) {
            int cn = blockIdx.x + (k + NS2) * NB;
            if (cn < nch) {
                int rn = N - cn * CH2; if (rn > CH2) rn = CH2;
                mb_tx(s2u(&mbs[s]), rn * 64);
                bulk_g2s(s2u(&inb[s][0]), (const void*)(X + (size_t)cn * CH2 * 16), rn * 64, s2u(&mbs[s]));
            }
        }
    }
#pragma unroll
    for (int of = 16; of > 0; of >>= 1) {
        float ov = __shfl_down_sync(0xffffffffu, best, of);
        int   oi = __shfl_down_sync(0xffffffffu, bi, of);
        sum += __shfl_down_sync(0xffffffffu, sum, of);
        if (ov > best || (ov == best && oi < bi)) { best = ov; bi = oi; }
    }
    __shared__ float wv[4], ws[4]; __shared__ int wi[4];
    int lane = t & 31, wid = t >> 5;
    if (lane == 0) { wv[wid] = best; wi[wid] = bi; ws[wid] = sum; }
    __syncthreads();
    if (t == 0) {
        float v = wv[0]; int ix = wi[0]; float s = ws[0];
#pragma unroll
        for (int w = 1; w < 4; w++) {
            if (wv[w] > v || (wv[w] == v && wi[w] < ix)) { v = wv[w]; ix = wi[w]; }
            s += ws[w];
        }
        g_aV[blockIdx.x] = v; g_aI[blockIdx.x] = ix; g_aS[blockIdx.x] = s;
    }
    __syncthreads();
    __shared__ int lastb;
    if (t == 0) { __threadfence(); lastb = (atomicAdd(cnt, 1) == NB - 1); }
    __syncthreads();
    if (lastb) fin_arg(t, which, out, cnt);
}

extern "C" void kernel_launch(void* const* d_in, const int* in_sizes, int n_in,
                              void* d_out, int out_size) {
    const float* jobs  = (const float*)d_in[0];
    const float* machs = (const float*)d_in[1];
    const void*  mask  = d_in[2];
    const float *jW1=(const float*)d_in[3], *jb1=(const float*)d_in[4], *jW2=(const float*)d_in[5], *jb2=(const float*)d_in[6];
    const float *mW1=(const float*)d_in[7], *mb1=(const float*)d_in[8], *mW2=(const float*)d_in[9], *mb2=(const float*)d_in[10];
    const float *ajWq=(const float*)d_in[11], *ajbq=(const float*)d_in[12], *ajWr=(const float*)d_in[13], *ajV=(const float*)d_in[14];
    const float *amWq=(const float*)d_in[15], *ambq=(const float*)d_in[16], *amWr=(const float*)d_in[17], *amV=(const float*)d_in[18];
    const float *jaWq=(const float*)d_in[19], *jabq=(const float*)d_in[20], *jaWr=(const float*)d_in[21], *jaV=(const float*)d_in[22];
    const float *maWq=(const float*)d_in[23], *mabq=(const float*)d_in[24], *maWr=(const float*)d_in[25], *maV=(const float*)d_in[26];
    const float *g1W=(const float*)d_in[27], *g1b=(const float*)d_in[28];
    const float *g2W=(const float*)d_in[29], *g2b=(const float*)d_in[30];
    const float *lastj=(const float*)d_in[31];
    int Nj = in_sizes[0] / 16;
    int Nm = in_sizes[1] / 16;
    float* out = (float*)d_out;

    k_emb<<<NB, BLOCK>>>(jobs, machs, Nj, Nm, jW1, jb1, jW2, jb2, mW1, mb1, mW2, mb2,
                         ajWr, ajV, ajWq, ajbq, amWr, amV, amWq, ambq, lastj, g1W, g1b);
    k_arg<<<NB, BLOCK>>>(0, Nj, jaWr, jaV, jaWq, jabq, mask, in_sizes[2], out);
    k_gl <<<NB, BLOCK>>>(Nj, Nm, ajWr, ajV, ajWq, ajbq, amWr, amV, amWq, ambq, g2W, g2b);
    k_arg<<<NB, BLOCK>>>(1, Nm, maWr, maV, maWq, mabq, nullptr, 0, out);
    (void)n_in; (void)out_size;
}

// round 7
// speedup vs baseline: 1.2027x; 1.0239x over previous
#include <cuda_runtime.h>
#include <math.h>

#define BLOCK 128
#define NBG 888          // grid for all big passes (6 CTAs/SM x 148)
#define BJG 600          // job-side blocks for emb/gl splits
#define NBMG (NBG - BJG)
typedef unsigned long long u64;

__device__ float g_Ej[16000000];
__device__ float g_Em[8000000];
__device__ float g_pJ[BJG * 17], g_pM[NBMG * 17];
__device__ float g_aV[NBG]; __device__ int g_aI[NBG]; __device__ float g_aS[NBG];
__device__ float g_g1[16], g_g2[16], g_ejs[16];
__device__ float g_logpj; __device__ int g_selj;
__device__ int g_c0, g_c1, g_c2, g_c3;

// ---------- packed f32x2 + fast math ----------
__device__ __forceinline__ u64 F2(u64 a, u64 b, u64 c) {
    u64 r; asm("fma.rn.f32x2 %0,%1,%2,%3;" : "=l"(r) : "l"(a), "l"(b), "l"(c)); return r;
}
__device__ __forceinline__ u64 pack2(float lo, float hi) {
    u64 r; asm("mov.b64 %0,{%1,%2};" : "=l"(r) : "f"(lo), "f"(hi)); return r;
}
__device__ __forceinline__ float2 unpack2(u64 v) {
    float2 r; asm("mov.b64 {%0,%1},%2;" : "=f"(r.x), "=f"(r.y) : "l"(v)); return r;
}
__device__ __forceinline__ float ftanh(float x) {
    float r; asm("tanh.approx.f32 %0,%1;" : "=f"(r) : "f"(x)); return r;
}

// ---------- bulk-async + mbarrier ----------
__device__ __forceinline__ unsigned s2u(const void* p) { return (unsigned)__cvta_generic_to_shared(p); }
__device__ __forceinline__ void mb_init(unsigned a, unsigned c) {
    asm volatile("mbarrier.init.shared.b64 [%0], %1;" :: "r"(a), "r"(c) : "memory");
}
__device__ __forceinline__ void mb_tx(unsigned a, unsigned bytes) {
    asm volatile("mbarrier.arrive.expect_tx.shared.b64 _, [%0], %1;" :: "r"(a), "r"(bytes) : "memory");
}
__device__ __forceinline__ void mb_wait(unsigned a, unsigned p) {
    asm volatile(
        "{\n\t.reg .pred P;\n"
        "WL%=:\n\t"
        "mbarrier.try_wait.parity.acquire.cta.shared::cta.b64 P, [%0], %1, 0x989680;\n\t"
        "@P bra WD%=;\n\t"
        "bra WL%=;\n"
        "WD%=:\n\t}"
        :: "r"(a), "r"(p) : "memory");
}
__device__ __forceinline__ void bulk_g2s(unsigned dst, const void* src, unsigned sz, unsigned mb) {
    asm volatile("cp.async.bulk.shared::cluster.global.mbarrier::complete_tx::bytes [%0], [%1], %2, [%3];"
                 :: "r"(dst), "l"(src), "r"(sz), "r"(mb) : "memory");
}
__device__ __forceinline__ void bulk_s2g(void* dst, unsigned src, unsigned sz) {
    asm volatile("cp.async.bulk.global.shared::cta.bulk_group [%0], [%1], %2;"
                 :: "l"(dst), "r"(src), "r"(sz) : "memory");
}
__device__ __forceinline__ void bulk_commit() { asm volatile("cp.async.bulk.commit_group;" ::: "memory"); }
__device__ __forceinline__ void bulk_wait1() { asm volatile("cp.async.bulk.wait_group 1;" ::: "memory"); }
__device__ __forceinline__ void bulk_wait0() { asm volatile("cp.async.bulk.wait_group 0;" ::: "memory"); }
__device__ __forceinline__ void fence_async() { asm volatile("fence.proxy.async.shared::cta;" ::: "memory"); }

// rotated-quarter 64B row LDS/STS
__device__ __forceinline__ void lds_row(unsigned sbase, int lr, u64 (&x)[8]) {
#pragma unroll
    for (int i = 0; i < 4; i++) {
        int q = (i + lr) & 3; u64 a, b;
        asm volatile("ld.shared.v2.b64 {%0,%1},[%2];" : "=l"(a), "=l"(b) : "r"(sbase + lr * 64 + q * 16));
        x[2 * q] = a; x[2 * q + 1] = b;
    }
}
__device__ __forceinline__ void sts_row(unsigned sbase, int lr, const u64 (&x)[8]) {
#pragma unroll
    for (int i = 0; i < 4; i++) {
        int q = (i + lr) & 3;
        asm volatile("st.shared.v2.b64 [%0],{%1,%2};" :: "r"(sbase + lr * 64 + q * 16),
                     "l"(x[2 * q]), "l"(x[2 * q + 1]) : "memory");
    }
}

__device__ __forceinline__ void redu17(float (&acc)[17], float* __restrict__ dst) {
#pragma unroll
    for (int k = 0; k < 17; k++)
#pragma unroll
        for (int o = 16; o > 0; o >>= 1) acc[k] += __shfl_down_sync(0xffffffffu, acc[k], o);
    __shared__ float red[4][17];
    int lane = threadIdx.x & 31, wid = threadIdx.x >> 5;
    if (lane == 0) {
#pragma unroll
        for (int k = 0; k < 17; k++) red[wid][k] = acc[k];
    }
    __syncthreads();
    if (threadIdx.x < 17) {
        float s = 0.f;
#pragma unroll
        for (int w = 0; w < 4; w++) s += red[w][threadIdx.x];
        dst[threadIdx.x] = s;
    }
}

// glimpse finalize (last block); scratch overlaid on the (dead) input smem buffer
struct FinGS { float tA[7][17]; float tB[7][17]; float sA[17]; float sB[17]; float cat[48]; float sGW[768]; };
__device__ void fin_g(int t, char* scr, int bj, int nbm, const float* __restrict__ q0,
                      const float* __restrict__ gW, const float* __restrict__ gb,
                      float* __restrict__ dst, int* cnt) {
    FinGS* S = (FinGS*)scr;
    int col = t % 17, grp = t / 17;
    __syncthreads();                 // inb fully dead before overlay
    if (grp < 7) {
        float a = 0.f, b = 0.f;
        for (int i = grp; i < bj;  i += 7) a += g_pJ[i * 17 + col];
        for (int i = grp; i < nbm; i += 7) b += g_pM[i * 17 + col];
        S->tA[grp][col] = a; S->tB[grp][col] = b;
    }
    for (int i = t; i < 768; i += BLOCK) S->sGW[i] = gW[i];
    __syncthreads();
    if (t < 17) {
        float a = 0.f, b = 0.f;
#pragma unroll
        for (int g = 0; g < 7; g++) { a += S->tA[g][t]; b += S->tB[g][t]; }
        S->sA[t] = a; S->sB[t] = b;
    }
    __syncthreads();
    if (t < 16) {
        S->cat[t] = q0[t];
        S->cat[16 + t] = S->sA[1 + t] / S->sA[0];
        S->cat[32 + t] = S->sB[1 + t] / S->sB[0];
    }
    __syncthreads();
    if (t < 16) {
        float g = gb[t];
#pragma unroll
        for (int d = 0; d < 48; d++) g += S->cat[d] * S->sGW[t * 48 + d];
        dst[t] = tanhf(g);
    }
    if (t == 0) *cnt = 0;
}

// argmax finalize
__device__ void fin_arg(int t, int which, int nb, float* __restrict__ out, int* cnt) {
    float bv = -3e38f, s = 0.f; int bi = 0x7fffffff;
    for (int i = t; i < nb; i += BLOCK) {
        float v = g_aV[i]; int ix = g_aI[i];
        if (v > bv || (v == bv && ix < bi)) { bv = v; bi = ix; }
        s += g_aS[i];
    }
#pragma unroll
    for (int o = 16; o > 0; o >>= 1) {
        float ov = __shfl_down_sync(0xffffffffu, bv, o);
        int   oi = __shfl_down_sync(0xffffffffu, bi, o);
        s += __shfl_down_sync(0xffffffffu, s, o);
        if (ov > bv || (ov == bv && oi < bi)) { bv = ov; bi = oi; }
    }
    __shared__ float wv[4], ws[4]; __shared__ int wi[4]; __shared__ int ssel;
    int lane = t & 31, wid = t >> 5;
    if (lane == 0) { wv[wid] = bv; wi[wid] = bi; ws[wid] = s; }
    __syncthreads();
    if (t == 0) {
        float v = wv[0]; int ix = wi[0]; float ss = ws[0];
#pragma unroll
        for (int w = 1; w < 4; w++) {
            if (wv[w] > v || (wv[w] == v && wi[w] < ix)) { v = wv[w]; ix = wi[w]; }
            ss += ws[w];
        }
        if (ix == 0x7fffffff) ix = 0;
        if (which == 0) { g_selj = ix; g_logpj = v - logf(ss); ssel = ix; }
        else { out[0] = (float)g_selj; out[1] = (float)ix; out[2] = g_logpj + (v - logf(ss)); }
        *cnt = 0;
    }
    __syncthreads();
    if (which == 0 && t < 16) g_ejs[t] = g_Ej[ssel * 16 + t];
}

// ================= pass 1: embed + glimpse-1 (1 row/thread, 2-stage in, 2-stage out) =================
#define CHE 128
#define CBE (CHE * 64)
__global__ void __launch_bounds__(BLOCK, 6) k_emb(
    const float* __restrict__ jobs, const float* __restrict__ machs, int Nj, int Nm,
    const float* __restrict__ jW1, const float* __restrict__ jb1,
    const float* __restrict__ jW2, const float* __restrict__ jb2,
    const float* __restrict__ mW1, const float* __restrict__ mb1,
    const float* __restrict__ mW2, const float* __restrict__ mb2,
    const float* __restrict__ ajWr, const float* __restrict__ ajV,
    const float* __restrict__ ajWq, const float* __restrict__ ajbq,
    const float* __restrict__ amWr, const float* __restrict__ amV,
    const float* __restrict__ amWq, const float* __restrict__ ambq,
    const float* __restrict__ lastj, const float* __restrict__ g1W, const float* __restrict__ g1b)
{
    __shared__ __align__(128) char inb[2][CBE];
    __shared__ __align__(128) char outb[2][CBE];
    __shared__ u64 mbs[2];
    __shared__ ulonglong2 sW1[64], sW2[64], sWr[64];
    __shared__ float sb1[16], sb2[16], sV[16], sQ[16];

    int t = threadIdx.x;
    int side = blockIdx.x >= BJG;
    int lb = side ? blockIdx.x - BJG : blockIdx.x;
    int nb = side ? NBMG : BJG;
    const float* X = side ? machs : jobs;
    int N = side ? Nm : Nj;
    float* Eo = side ? g_Em : g_Ej;
    float* part = (side ? g_pM : g_pJ) + lb * 17;
    const float* W1 = side ? mW1 : jW1; const float* b1 = side ? mb1 : jb1;
    const float* W2 = side ? mW2 : jW2; const float* b2 = side ? mb2 : jb2;
    const float* Wr = side ? amWr : ajWr; const float* V = side ? amV : ajV;
    const float* Wq = side ? amWq : ajWq; const float* bq = side ? ambq : ajbq;

    if (t < 64) {
        sW1[t] = ((const ulonglong2*)W1)[t];
        sW2[t] = ((const ulonglong2*)W2)[t];
        sWr[t] = ((const ulonglong2*)Wr)[t];
    }
    if (t < 16) {
        sb1[t] = b1[t]; sb2[t] = b2[t]; sV[t] = V[t];
        float q = bq[t];
#pragma unroll
        for (int d = 0; d < 16; d++) q += lastj[d] * Wq[t * 16 + d];
        sQ[t] = q;
    }
    if (t == 0) { mb_init(s2u(&mbs[0]), 1); mb_init(s2u(&mbs[1]), 1); }
    __syncthreads();

    int nch = (N + CHE - 1) / CHE;
    if (t == 0) {
#pragma unroll
        for (int s = 0; s < 2; s++) {
            int c = lb + s * nb;
            if (c < nch) {
                int rows = N - c * CHE; if (rows > CHE) rows = CHE;
                mb_tx(s2u(&mbs[s]), rows * 64);
                bulk_g2s(s2u(&inb[s][0]), (const void*)(X + (size_t)c * CHE * 16), rows * 64, s2u(&mbs[s]));
            }
        }
    }

    float S = 0.f; u64 Wa[8];
#pragma unroll
    for (int k = 0; k < 8; k++) Wa[k] = 0ull;

    for (int k = 0; ; k++) {
        int c = lb + k * nb;
        if (c >= nch) break;
        int s = k & 1; unsigned ph = (unsigned)((k >> 1) & 1);
        mb_wait(s2u(&mbs[s]), ph);

        int row0 = c * CHE;
        int rows = N - row0; if (rows > CHE) rows = CHE;
        bool ok = t < rows;
        u64 x[8], y[8];
        if (ok) lds_row(s2u(&inb[s][0]), t, x);
        else { for (int i = 0; i < 8; i++) x[i] = 0ull; }

        // layer 1: y = tanh(x @ W1^T + b1)
        {
            float tp = 0.f;
#pragma unroll
            for (int j = 0; j < 16; j++) {
                u64 a = 0ull;
#pragma unroll
                for (int dd = 0; dd < 4; dd++) { ulonglong2 w = sW1[j * 4 + dd]; a = F2(x[2 * dd], w.x, a); a = F2(x[2 * dd + 1], w.y, a); }
                float2 u = unpack2(a); float tt = ftanh(u.x + u.y + sb1[j]);
                if (j & 1) y[j >> 1] = pack2(tp, tt); else tp = tt;
            }
        }
        // layer 2: x = tanh(y @ W2^T + b2) = embedding
        {
            float tp = 0.f;
#pragma unroll
            for (int j = 0; j < 16; j++) {
                u64 a = 0ull;
#pragma unroll
                for (int dd = 0; dd < 4; dd++) { ulonglong2 w = sW2[j * 4 + dd]; a = F2(y[2 * dd], w.x, a); a = F2(y[2 * dd + 1], w.y, a); }
                float2 u = unpack2(a); float tt = ftanh(u.x + u.y + sb2[j]);
                if (j & 1) x[j >> 1] = pack2(tp, tt); else tp = tt;
            }
        }
        // E out via bulk store
        int os = k & 1;
        if (k >= 2 && t == 0) bulk_wait1();
        __syncthreads();
        if (ok) sts_row(s2u(&outb[os][0]), t, x);
        fence_async();
        // glimpse-1: l = V . tanh(q' + E@Wr^T); accumulate exp(l), exp(l)*E
        if (ok) {
            float l = 0.f;
#pragma unroll
            for (int j = 0; j < 16; j++) {
                u64 a = 0ull;
#pragma unroll
                for (int dd = 0; dd < 4; dd++) { ulonglong2 w = sWr[j * 4 + dd]; a = F2(x[2 * dd], w.x, a); a = F2(x[2 * dd + 1], w.y, a); }
                float2 u = unpack2(a); l += sV[j] * ftanh(u.x + u.y + sQ[j]);
            }
            float w = __expf(l); S += w;
            u64 wp = pack2(w, w);
#pragma unroll
            for (int kk = 0; kk < 8; kk++) Wa[kk] = F2(wp, x[kk], Wa[kk]);
        }
        __syncthreads();
        if (t == 0) {
            bulk_s2g((void*)(Eo + (size_t)row0 * 16), s2u(&outb[os][0]), rows * 64);
            bulk_commit();
            int cn = lb + (k + 2) * nb;
            if (cn < nch) {
                int rn = N - cn * CHE; if (rn > CHE) rn = CHE;
                mb_tx(s2u(&mbs[s]), rn * 64);
                bulk_g2s(s2u(&inb[s][0]), (const void*)(X + (size_t)cn * CHE * 16), rn * 64, s2u(&mbs[s]));
            }
        }
    }
    if (t == 0) bulk_wait0();

    float acc[17]; acc[0] = S;
#pragma unroll
    for (int k = 0; k < 8; k++) { float2 u = unpack2(Wa[k]); acc[1 + 2 * k] = u.x; acc[2 + 2 * k] = u.y; }
    redu17(acc, part);
    __syncthreads();
    __shared__ int lastb;
    if (t == 0) { __threadfence(); lastb = (atomicAdd(&g_c0, 1) == NBG - 1); }
    __syncthreads();
    if (lastb) fin_g(t, &inb[0][0], BJG, NBMG, lastj, g1W, g1b, g_g1, &g_c0);
}

// ================= pass 3: glimpse-2 over stored E (2 rows/thread, 2-stage) =================
#define CHG 256
#define CBG (CHG * 64)
__global__ void __launch_bounds__(BLOCK, 6) k_gl(
    int Nj, int Nm,
    const float* __restrict__ ajWr, const float* __restrict__ ajV,
    const float* __restrict__ ajWq, const float* __restrict__ ajbq,
    const float* __restrict__ amWr, const float* __restrict__ amV,
    const float* __restrict__ amWq, const float* __restrict__ ambq,
    const float* __restrict__ g2W, const float* __restrict__ g2b)
{
    __shared__ __align__(128) char inb[2][CBG];
    __shared__ u64 mbs[2];
    __shared__ ulonglong2 sWr[64];
    __shared__ float sV[16], sQ[16];

    int t = threadIdx.x;
    int side = blockIdx.x >= BJG;
    int lb = side ? blockIdx.x - BJG : blockIdx.x;
    int nb = side ? NBMG : BJG;
    const float* X = side ? g_Em : g_Ej;
    int N = side ? Nm : Nj;
    float* part = (side ? g_pM : g_pJ) + lb * 17;
    const float* Wr = side ? amWr : ajWr; const float* V = side ? amV : ajV;
    const float* Wq = side ? amWq : ajWq; const float* bq = side ? ambq : ajbq;

    if (t < 64) sWr[t] = ((const ulonglong2*)Wr)[t];
    if (t < 16) {
        sV[t] = V[t];
        float q = bq[t];
#pragma unroll
        for (int d = 0; d < 16; d++) q += g_ejs[d] * Wq[t * 16 + d];
        sQ[t] = q;
    }
    if (t == 0) { mb_init(s2u(&mbs[0]), 1); mb_init(s2u(&mbs[1]), 1); }
    __syncthreads();

    int nch = (N + CHG - 1) / CHG;
    if (t == 0) {
#pragma unroll
        for (int s = 0; s < 2; s++) {
            int c = lb + s * nb;
            if (c < nch) {
                int rows = N - c * CHG; if (rows > CHG) rows = CHG;
                mb_tx(s2u(&mbs[s]), rows * 64);
                bulk_g2s(s2u(&inb[s][0]), (const void*)(X + (size_t)c * CHG * 16), rows * 64, s2u(&mbs[s]));
            }
        }
    }

    float S = 0.f; u64 Wa[8];
#pragma unroll
    for (int k = 0; k < 8; k++) Wa[k] = 0ull;

    for (int k = 0; ; k++) {
        int c = lb + k * nb;
        if (c >= nch) break;
        int s = k & 1; unsigned ph = (unsigned)((k >> 1) & 1);
        mb_wait(s2u(&mbs[s]), ph);

        int row0 = c * CHG;
        int rows = N - row0; if (rows > CHG) rows = CHG;
        u64 x[2][8]; bool ok[2];
        ok[0] = t < rows; ok[1] = t + BLOCK < rows;
#pragma unroll
        for (int r = 0; r < 2; r++) {
            if (ok[r]) lds_row(s2u(&inb[s][0]), t + r * BLOCK, x[r]);
            else { for (int i = 0; i < 8; i++) x[r][i] = 0ull; }
        }
        float l0 = 0.f, l1 = 0.f;
#pragma unroll
        for (int j = 0; j < 16; j++) {
            u64 a0 = 0ull, a1 = 0ull;
#pragma unroll
            for (int dd = 0; dd < 4; dd++) {
                ulonglong2 w = sWr[j * 4 + dd];
                a0 = F2(x[0][2 * dd], w.x, a0); a0 = F2(x[0][2 * dd + 1], w.y, a0);
                a1 = F2(x[1][2 * dd], w.x, a1); a1 = F2(x[1][2 * dd + 1], w.y, a1);
            }
            float2 u0 = unpack2(a0), u1 = unpack2(a1); float vj = sV[j], qj = sQ[j];
            l0 += vj * ftanh(u0.x + u0.y + qj);
            l1 += vj * ftanh(u1.x + u1.y + qj);
        }
        if (ok[0]) {
            float w = __expf(l0); S += w; u64 wp = pack2(w, w);
#pragma unroll
            for (int kk = 0; kk < 8; kk++) Wa[kk] = F2(wp, x[0][kk], Wa[kk]);
        }
        if (ok[1]) {
            float w = __expf(l1); S += w; u64 wp = pack2(w, w);
#pragma unroll
            for (int kk = 0; kk < 8; kk++) Wa[kk] = F2(wp, x[1][kk], Wa[kk]);
        }
        __syncthreads();
        if (t == 0) {
            int cn = lb + (k + 2) * nb;
            if (cn < nch) {
                int rn = N - cn * CHG; if (rn > CHG) rn = CHG;
                mb_tx(s2u(&mbs[s]), rn * 64);
                bulk_g2s(s2u(&inb[s][0]), (const void*)(X + (size_t)cn * CHG * 16), rn * 64, s2u(&mbs[s]));
            }
        }
    }

    float acc[17]; acc[0] = S;
#pragma unroll
    for (int k = 0; k < 8; k++) { float2 u = unpack2(Wa[k]); acc[1 + 2 * k] = u.x; acc[2 + 2 * k] = u.y; }
    redu17(acc, part);
    __syncthreads();
    __shared__ int lastb;
    if (t == 0) { __threadfence(); lastb = (atomicAdd(&g_c2, 1) == NBG - 1); }
    __syncthreads();
    if (lastb) fin_g(t, &inb[0][0], BJG, NBMG, g_ejs, g2W, g2b, g_g2, &g_c2);
}

// ================= passes 2 & 4: pointer logits -> argmax + sumexp =================
__global__ void __launch_bounds__(BLOCK, 6) k_arg(
    int which, int N,
    const float* __restrict__ Wr, const float* __restrict__ V,
    const float* __restrict__ Wq, const float* __restrict__ bq,
    const void* __restrict__ maskp, int nmask, float* __restrict__ out)
{
    __shared__ __align__(128) char inb[2][CBG];
    __shared__ u64 mbs[2];
    __shared__ ulonglong2 sWr[64];
    __shared__ float sV[16], sQ[16];
    __shared__ int smk;

    int t = threadIdx.x;
    const float* X = which ? g_Em : g_Ej;
    const float* qs = which ? g_g2 : g_g1;
    int* cnt = which ? &g_c3 : &g_c1;

    if (t == 0) smk = 0;
    if (t < 64) sWr[t] = ((const ulonglong2*)Wr)[t];
    if (t < 16) {
        sV[t] = V[t];
        float q = bq[t];
#pragma unroll
        for (int d = 0; d < 16; d++) q += qs[d] * Wq[t * 16 + d];
        sQ[t] = q;
    }
    if (t == 0) { mb_init(s2u(&mbs[0]), 1); mb_init(s2u(&mbs[1]), 1); }
    __syncthreads();
    // mask dtype detect: 0 = 4-byte elems (int32/float32), 1 = byte bools
    if (maskp) {
        int words = nmask >> 2; if (words > 4096) words = 4096;
        int f = 0;
        for (int i = t; i < words; i += BLOCK) {
            unsigned w = ((const unsigned*)maskp)[i];
            if (w != 0u && w != 1u && w != 0x3F800000u) f = 1;
        }
        if (f) atomicOr(&smk, 1);
    }
    __syncthreads();
    int mk = smk;

    int nch = (N + CHG - 1) / CHG;
    if (t == 0) {
#pragma unroll
        for (int s = 0; s < 2; s++) {
            int c = blockIdx.x + s * NBG;
            if (c < nch) {
                int rows = N - c * CHG; if (rows > CHG) rows = CHG;
                mb_tx(s2u(&mbs[s]), rows * 64);
                bulk_g2s(s2u(&inb[s][0]), (const void*)(X + (size_t)c * CHG * 16), rows * 64, s2u(&mbs[s]));
            }
        }
    }

    float best = -3e38f, sum = 0.f; int bi = 0x7fffffff;
    for (int k = 0; ; k++) {
        int c = blockIdx.x + k * NBG;
        if (c >= nch) break;
        int s = k & 1; unsigned ph = (unsigned)((k >> 1) & 1);
        mb_wait(s2u(&mbs[s]), ph);

        int row0 = c * CHG;
        int rows = N - row0; if (rows > CHG) rows = CHG;
        u64 x[2][8]; bool ok[2];
        ok[0] = t < rows; ok[1] = t + BLOCK < rows;
#pragma unroll
        for (int r = 0; r < 2; r++) {
            if (ok[r]) lds_row(s2u(&inb[s][0]), t + r * BLOCK, x[r]);
            else { for (int i = 0; i < 8; i++) x[r][i] = 0ull; }
        }
        float l0 = 0.f, l1 = 0.f;
#pragma unroll
        for (int j = 0; j < 16; j++) {
            u64 a0 = 0ull, a1 = 0ull;
#pragma unroll
            for (int dd = 0; dd < 4; dd++) {
                ulonglong2 w = sWr[j * 4 + dd];
                a0 = F2(x[0][2 * dd], w.x, a0); a0 = F2(x[0][2 * dd + 1], w.y, a0);
                a1 = F2(x[1][2 * dd], w.x, a1); a1 = F2(x[1][2 * dd + 1], w.y, a1);
            }
            float2 u0 = unpack2(a0), u1 = unpack2(a1); float vj = sV[j], qj = sQ[j];
            l0 += vj * ftanh(u0.x + u0.y + qj);
            l1 += vj * ftanh(u1.x + u1.y + qj);
        }
#pragma unroll
        for (int r = 0; r < 2; r++) if (ok[r]) {
            int row = row0 + t + r * BLOCK;
            float l = r ? l1 : l0;
            bool pass = true;
            if (maskp) {
                if (mk) pass = ((const unsigned char*)maskp)[row] != 0;
                else    pass = ((const unsigned*)maskp)[row] != 0u;
            }
            if (pass) {
                sum += __expf(l);
                if (l > best) { best = l; bi = row; }
            }
        }
        __syncthreads();
        if (t == 0) {
            int cn = blockIdx.x + (k + 2) * NBG;
            if (cn < nch) {
                int rn = N - cn * CHG; if (rn > CHG) rn = CHG;
                mb_tx(s2u(&mbs[s]), rn * 64);
                bulk_g2s(s2u(&inb[s][0]), (const void*)(X + (size_t)cn * CHG * 16), rn * 64, s2u(&mbs[s]));
            }
        }
    }
#pragma unroll
    for (int of = 16; of > 0; of >>= 1) {
        float ov = __shfl_down_sync(0xffffffffu, best, of);
        int   oi = __shfl_down_sync(0xffffffffu, bi, of);
        sum += __shfl_down_sync(0xffffffffu, sum, of);
        if (ov > best || (ov == best && oi < bi)) { best = ov; bi = oi; }
    }
    __shared__ float wv[4], ws[4]; __shared__ int wi[4];
    int lane = t & 31, wid = t >> 5;
    if (lane == 0) { wv[wid] = best; wi[wid] = bi; ws[wid] = sum; }
    __syncthreads();
    if (t == 0) {
        float v = wv[0]; int ix = wi[0]; float s = ws[0];
#pragma unroll
        for (int w = 1; w < 4; w++) {
            if (wv[w] > v || (wv[w] == v && wi[w] < ix)) { v = wv[w]; ix = wi[w]; }
            s += ws[w];
        }
        g_aV[blockIdx.x] = v; g_aI[blockIdx.x] = ix; g_aS[blockIdx.x] = s;
    }
    __syncthreads();
    __shared__ int lastb;
    if (t == 0) { __threadfence(); lastb = (atomicAdd(cnt, 1) == NBG - 1); }
    __syncthreads();
    if (lastb) fin_arg(t, which, NBG, out, cnt);
}

extern "C" void kernel_launch(void* const* d_in, const int* in_sizes, int n_in,
                              void* d_out, int out_size) {
    const float* jobs  = (const float*)d_in[0];
    const float* machs = (const float*)d_in[1];
    const void*  mask  = d_in[2];
    const float *jW1=(const float*)d_in[3], *jb1=(const float*)d_in[4], *jW2=(const float*)d_in[5], *jb2=(const float*)d_in[6];
    const float *mW1=(const float*)d_in[7], *mb1=(const float*)d_in[8], *mW2=(const float*)d_in[9], *mb2=(const float*)d_in[10];
    const float *ajWq=(const float*)d_in[11], *ajbq=(const float*)d_in[12], *ajWr=(const float*)d_in[13], *ajV=(const float*)d_in[14];
    const float *amWq=(const float*)d_in[15], *ambq=(const float*)d_in[16], *amWr=(const float*)d_in[17], *amV=(const float*)d_in[18];
    const float *jaWq=(const float*)d_in[19], *jabq=(const float*)d_in[20], *jaWr=(const float*)d_in[21], *jaV=(const float*)d_in[22];
    const float *maWq=(const float*)d_in[23], *mabq=(const float*)d_in[24], *maWr=(const float*)d_in[25], *maV=(const float*)d_in[26];
    const float *g1W=(const float*)d_in[27], *g1b=(const float*)d_in[28];
    const float *g2W=(const float*)d_in[29], *g2b=(const float*)d_in[30];
    const float *lastj=(const float*)d_in[31];
    int Nj = in_sizes[0] / 16;
    int Nm = in_sizes[1] / 16;
    float* out = (float*)d_out;

    k_emb<<<NBG, BLOCK>>>(jobs, machs, Nj, Nm, jW1, jb1, jW2, jb2, mW1, mb1, mW2, mb2,
                          ajWr, ajV, ajWq, ajbq, amWr, amV, amWq, ambq, lastj, g1W, g1b);
    k_arg<<<NBG, BLOCK>>>(0, Nj, jaWr, jaV, jaWq, jabq, mask, in_sizes[2], out);
    k_gl <<<NBG, BLOCK>>>(Nj, Nm, ajWr, ajV, ajWq, ajbq, amWr, amV, amWq, ambq, g2W, g2b);
    k_arg<<<NBG, BLOCK>>>(1, Nm, maWr, maV, maWq, mabq, nullptr, 0, out);
    (void)n_in; (void)out_size;
}

// round 9
// speedup vs baseline: 1.2435x; 1.0339x over previous
#include <cuda_runtime.h>
#include <math.h>

#define BLOCK 128
#define NBG 888
#define BJG 592
#define NBMG (NBG - BJG)
typedef unsigned long long u64;

__device__ float g_Ej[16000000];
__device__ float g_Em[8000000];
__device__ float g_pJ[BJG * 17], g_pM[NBMG * 17];
__device__ float g_aV[NBG]; __device__ int g_aI[NBG]; __device__ float g_aS[NBG];
__device__ float g_g1[16], g_g2[16], g_ejs[16];
__device__ float g_logpj; __device__ int g_selj;
__device__ int g_c0, g_c1, g_c2, g_c3;

// ---------- packed f32x2 + fast math ----------
__device__ __forceinline__ u64 F2(u64 a, u64 b, u64 c) {
    u64 r; asm("fma.rn.f32x2 %0,%1,%2,%3;" : "=l"(r) : "l"(a), "l"(b), "l"(c)); return r;
}
__device__ __forceinline__ u64 pack2(float lo, float hi) {
    u64 r; asm("mov.b64 %0,{%1,%2};" : "=l"(r) : "f"(lo), "f"(hi)); return r;
}
__device__ __forceinline__ float2 unpack2(u64 v) {
    float2 r; asm("mov.b64 {%0,%1},%2;" : "=f"(r.x), "=f"(r.y) : "l"(v)); return r;
}
__device__ __forceinline__ float ftanh(float x) {
    float r; asm("tanh.approx.f32 %0,%1;" : "=f"(r) : "f"(x)); return r;
}

// ---------- bulk-async + mbarrier ----------
__device__ __forceinline__ unsigned s2u(const void* p) { return (unsigned)__cvta_generic_to_shared(p); }
__device__ __forceinline__ void mb_init(unsigned a, unsigned c) {
    asm volatile("mbarrier.init.shared.b64 [%0], %1;" :: "r"(a), "r"(c) : "memory");
}
__device__ __forceinline__ void mb_tx(unsigned a, unsigned bytes) {
    asm volatile("mbarrier.arrive.expect_tx.shared.b64 _, [%0], %1;" :: "r"(a), "r"(bytes) : "memory");
}
__device__ __forceinline__ void mb_wait(unsigned a, unsigned p) {
    asm volatile(
        "{\n\t.reg .pred P;\n"
        "WL%=:\n\t"
        "mbarrier.try_wait.parity.acquire.cta.shared::cta.b64 P, [%0], %1, 0x989680;\n\t"
        "@P bra WD%=;\n\t"
        "bra WL%=;\n"
        "WD%=:\n\t}"
        :: "r"(a), "r"(p) : "memory");
}
__device__ __forceinline__ void bulk_g2s(unsigned dst, const void* src, unsigned sz, unsigned mb) {
    asm volatile("cp.async.bulk.shared::cluster.global.mbarrier::complete_tx::bytes [%0], [%1], %2, [%3];"
                 :: "r"(dst), "l"(src), "r"(sz), "r"(mb) : "memory");
}
__device__ __forceinline__ void bulk_s2g(void* dst, unsigned src, unsigned sz) {
    asm volatile("cp.async.bulk.global.shared::cta.bulk_group [%0], [%1], %2;"
                 :: "l"(dst), "r"(src), "r"(sz) : "memory");
}
__device__ __forceinline__ void bulk_commit() { asm volatile("cp.async.bulk.commit_group;" ::: "memory"); }
__device__ __forceinline__ void bulk_wait1() { asm volatile("cp.async.bulk.wait_group 1;" ::: "memory"); }
__device__ __forceinline__ void bulk_wait0() { asm volatile("cp.async.bulk.wait_group 0;" ::: "memory"); }
__device__ __forceinline__ void fence_async() { asm volatile("fence.proxy.async.shared::cta;" ::: "memory"); }

// rotated-quarter 64B row LDS/STS
__device__ __forceinline__ void lds_row(unsigned sbase, int lr, u64 (&x)[8]) {
#pragma unroll
    for (int i = 0; i < 4; i++) {
        int q = (i + lr) & 3; u64 a, b;
        asm volatile("ld.shared.v2.b64 {%0,%1},[%2];" : "=l"(a), "=l"(b) : "r"(sbase + lr * 64 + q * 16));
        x[2 * q] = a; x[2 * q + 1] = b;
    }
}
__device__ __forceinline__ void sts_row(unsigned sbase, int lr, const u64 (&x)[8]) {
#pragma unroll
    for (int i = 0; i < 4; i++) {
        int q = (i + lr) & 3;
        asm volatile("st.shared.v2.b64 [%0],{%1,%2};" :: "r"(sbase + lr * 64 + q * 16),
                     "l"(x[2 * q]), "l"(x[2 * q + 1]) : "memory");
    }
}

__device__ __forceinline__ void redu17(float (&acc)[17], float* __restrict__ dst) {
#pragma unroll
    for (int k = 0; k < 17; k++)
#pragma unroll
        for (int o = 16; o > 0; o >>= 1) acc[k] += __shfl_down_sync(0xffffffffu, acc[k], o);
    __shared__ float red[4][17];
    int lane = threadIdx.x & 31, wid = threadIdx.x >> 5;
    if (lane == 0) {
#pragma unroll
        for (int k = 0; k < 17; k++) red[wid][k] = acc[k];
    }
    __syncthreads();
    if (threadIdx.x < 17) {
        float s = 0.f;
#pragma unroll
        for (int w = 0; w < 4; w++) s += red[w][threadIdx.x];
        dst[threadIdx.x] = s;
    }
}

// glimpse finalize (last block); scratch overlaid on dead input smem
struct FinGS { float tA[7][17]; float tB[7][17]; float sA[17]; float sB[17]; float cat[48]; float sGW[768]; };
__device__ void fin_g(int t, char* scr, const float* __restrict__ q0,
                      const float* __restrict__ gW, const float* __restrict__ gb,
                      float* __restrict__ dst, int* cnt) {
    FinGS* S = (FinGS*)scr;
    int col = t % 17, grp = t / 17;
    __syncthreads();
    if (grp < 7) {
        float a = 0.f, b = 0.f;
        for (int i = grp; i < BJG;  i += 7) a += g_pJ[i * 17 + col];
        for (int i = grp; i < NBMG; i += 7) b += g_pM[i * 17 + col];
        S->tA[grp][col] = a; S->tB[grp][col] = b;
    }
    for (int i = t; i < 768; i += BLOCK) S->sGW[i] = gW[i];
    __syncthreads();
    if (t < 17) {
        float a = 0.f, b = 0.f;
#pragma unroll
        for (int g = 0; g < 7; g++) { a += S->tA[g][t]; b += S->tB[g][t]; }
        S->sA[t] = a; S->sB[t] = b;
    }
    __syncthreads();
    if (t < 16) {
        S->cat[t] = q0[t];
        S->cat[16 + t] = S->sA[1 + t] / S->sA[0];
        S->cat[32 + t] = S->sB[1 + t] / S->sB[0];
    }
    __syncthreads();
    if (t < 16) {
        float g = gb[t];
#pragma unroll
        for (int d = 0; d < 48; d++) g += S->cat[d] * S->sGW[t * 48 + d];
        dst[t] = tanhf(g);
    }
    if (t == 0) *cnt = 0;
}

__device__ void fin_arg(int t, int which, float* __restrict__ out, int* cnt) {
    float bv = -3e38f, s = 0.f; int bi = 0x7fffffff;
    for (int i = t; i < NBG; i += BLOCK) {
        float v = g_aV[i]; int ix = g_aI[i];
        if (v > bv || (v == bv && ix < bi)) { bv = v; bi = ix; }
        s += g_aS[i];
    }
#pragma unroll
    for (int o = 16; o > 0; o >>= 1) {
        float ov = __shfl_down_sync(0xffffffffu, bv, o);
        int   oi = __shfl_down_sync(0xffffffffu, bi, o);
        s += __shfl_down_sync(0xffffffffu, s, o);
        if (ov > bv || (ov == bv && oi < bi)) { bv = ov; bi = oi; }
    }
    __shared__ float wv[4], ws[4]; __shared__ int wi[4]; __shared__ int ssel;
    int lane = t & 31, wid = t >> 5;
    if (lane == 0) { wv[wid] = bv; wi[wid] = bi; ws[wid] = s; }
    __syncthreads();
    if (t == 0) {
        float v = wv[0]; int ix = wi[0]; float ss = ws[0];
#pragma unroll
        for (int w = 1; w < 4; w++) {
            if (wv[w] > v || (wv[w] == v && wi[w] < ix)) { v = wv[w]; ix = wi[w]; }
            ss += ws[w];
        }
        if (ix == 0x7fffffff) ix = 0;
        if (which == 0) { g_selj = ix; g_logpj = v - logf(ss); ssel = ix; }
        else { out[0] = (float)g_selj; out[1] = (float)ix; out[2] = g_logpj + (v - logf(ss)); }
        *cnt = 0;
    }
    __syncthreads();
    if (which == 0 && t < 16) g_ejs[t] = g_Ej[ssel * 16 + t];
}

// ================= pass 1: embed + glimpse-1 (contiguous spans, 2-in/2-out) =================
#define CHE 128
#define CBE (CHE * 64)
__global__ void __launch_bounds__(BLOCK, 6) k_emb(
    const float* __restrict__ jobs, const float* __restrict__ machs, int Nj, int Nm,
    const float* __restrict__ jW1, const float* __restrict__ jb1,
    const float* __restrict__ jW2, const float* __restrict__ jb2,
    const float* __restrict__ mW1, const float* __restrict__ mb1,
    const float* __restrict__ mW2, const float* __restrict__ mb2,
    const float* __restrict__ ajWr, const float* __restrict__ ajV,
    const float* __restrict__ ajWq, const float* __restrict__ ajbq,
    const float* __restrict__ amWr, const float* __restrict__ amV,
    const float* __restrict__ amWq, const float* __restrict__ ambq,
    const float* __restrict__ lastj, const float* __restrict__ g1W, const float* __restrict__ g1b)
{
    __shared__ __align__(128) char inb[2][CBE];
    __shared__ __align__(128) char outb[2][CBE];
    __shared__ u64 mbs[2];
    __shared__ ulonglong2 sW1[64], sW2[64], sWr[64];
    __shared__ float sb1[16], sb2[16], sV[16], sQ[16];

    int t = threadIdx.x;
    int side = blockIdx.x >= BJG;
    int lb = side ? blockIdx.x - BJG : blockIdx.x;
    int nb = side ? NBMG : BJG;
    const float* X = side ? machs : jobs;
    int N = side ? Nm : Nj;
    float* Eo = side ? g_Em : g_Ej;
    float* part = (side ? g_pM : g_pJ) + lb * 17;
    const float* W1 = side ? mW1 : jW1; const float* b1 = side ? mb1 : jb1;
    const float* W2 = side ? mW2 : jW2; const float* b2 = side ? mb2 : jb2;
    const float* Wr = side ? amWr : ajWr; const float* V = side ? amV : ajV;
    const float* Wq = side ? amWq : ajWq; const float* bq = side ? ambq : ajbq;

    if (t < 64) {
        sW1[t] = ((const ulonglong2*)W1)[t];
        sW2[t] = ((const ulonglong2*)W2)[t];
        sWr[t] = ((const ulonglong2*)Wr)[t];
    }
    if (t < 16) {
        sb1[t] = b1[t]; sb2[t] = b2[t]; sV[t] = V[t];
        float q = bq[t];
#pragma unroll
        for (int d = 0; d < 16; d++) q += lastj[d] * Wq[t * 16 + d];
        sQ[t] = q;
    }
    if (t == 0) { mb_init(s2u(&mbs[0]), 1); mb_init(s2u(&mbs[1]), 1); }
    __syncthreads();

    int nch = (N + CHE - 1) / CHE;
    int c0 = (int)(((long long)lb * nch) / nb);
    int c1 = (int)(((long long)(lb + 1) * nch) / nb);
    int myn = c1 - c0;

    if (t == 0) {
#pragma unroll
        for (int s = 0; s < 2; s++) {
            int c = c0 + s;
            if (s < myn) {
                int rows = N - c * CHE; if (rows > CHE) rows = CHE;
                mb_tx(s2u(&mbs[s]), rows * 64);
                bulk_g2s(s2u(&inb[s][0]), (const void*)(X + (size_t)c * CHE * 16), rows * 64, s2u(&mbs[s]));
            }
        }
    }

    float S = 0.f; u64 Wa[8];
#pragma unroll
    for (int k = 0; k < 8; k++) Wa[k] = 0ull;

    for (int k = 0; k < myn; k++) {
        int c = c0 + k;
        int s = k & 1; unsigned ph = (unsigned)((k >> 1) & 1);
        mb_wait(s2u(&mbs[s]), ph);

        int row0 = c * CHE;
        int rows = N - row0; if (rows > CHE) rows = CHE;
        bool ok = t < rows;
        u64 x[8], y[8];
        if (ok) lds_row(s2u(&inb[s][0]), t, x);
        else { for (int i = 0; i < 8; i++) x[i] = 0ull; }

        {   // layer 1
            float tp = 0.f;
#pragma unroll
            for (int j = 0; j < 16; j++) {
                u64 a = 0ull;
#pragma unroll
                for (int dd = 0; dd < 4; dd++) { ulonglong2 w = sW1[j * 4 + dd]; a = F2(x[2 * dd], w.x, a); a = F2(x[2 * dd + 1], w.y, a); }
                float2 u = unpack2(a); float tt = ftanh(u.x + u.y + sb1[j]);
                if (j & 1) y[j >> 1] = pack2(tp, tt); else tp = tt;
            }
        }
        {   // layer 2 -> embedding
            float tp = 0.f;
#pragma unroll
            for (int j = 0; j < 16; j++) {
                u64 a = 0ull;
#pragma unroll
                for (int dd = 0; dd < 4; dd++) { ulonglong2 w = sW2[j * 4 + dd]; a = F2(y[2 * dd], w.x, a); a = F2(y[2 * dd + 1], w.y, a); }
                float2 u = unpack2(a); float tt = ftanh(u.x + u.y + sb2[j]);
                if (j & 1) x[j >> 1] = pack2(tp, tt); else tp = tt;
            }
        }
        int os = k & 1;
        if (k >= 2 && t == 0) bulk_wait1();
        __syncthreads();
        if (ok) sts_row(s2u(&outb[os][0]), t, x);
        fence_async();
        if (ok) {   // glimpse-1
            float l = 0.f;
#pragma unroll
            for (int j = 0; j < 16; j++) {
                u64 a = 0ull;
#pragma unroll
                for (int dd = 0; dd < 4; dd++) { ulonglong2 w = sWr[j * 4 + dd]; a = F2(x[2 * dd], w.x, a); a = F2(x[2 * dd + 1], w.y, a); }
                float2 u = unpack2(a); l += sV[j] * ftanh(u.x + u.y + sQ[j]);
            }
            float w = __expf(l); S += w;
            u64 wp = pack2(w, w);
#pragma unroll
            for (int kk = 0; kk < 8; kk++) Wa[kk] = F2(wp, x[kk], Wa[kk]);
        }
        __syncthreads();
        if (t == 0) {
            bulk_s2g((void*)(Eo + (size_t)row0 * 16), s2u(&outb[os][0]), rows * 64);
            bulk_commit();
            int kn = k + 2;
            if (kn < myn) {
                int cn = c0 + kn;
                int rn = N - cn * CHE; if (rn > CHE) rn = CHE;
                mb_tx(s2u(&mbs[s]), rn * 64);
                bulk_g2s(s2u(&inb[s][0]), (const void*)(X + (size_t)cn * CHE * 16), rn * 64, s2u(&mbs[s]));
            }
        }
    }
    if (t == 0) bulk_wait0();

    float acc[17]; acc[0] = S;
#pragma unroll
    for (int k = 0; k < 8; k++) { float2 u = unpack2(Wa[k]); acc[1 + 2 * k] = u.x; acc[2 + 2 * k] = u.y; }
    redu17(acc, part);
    __syncthreads();
    __shared__ int lastb;
    if (t == 0) { __threadfence(); lastb = (atomicAdd(&g_c0, 1) == NBG - 1); }
    __syncthreads();
    if (lastb) fin_g(t, &inb[0][0], lastj, g1W, g1b, g_g1, &g_c0);
}

// ================= pass 3: glimpse-2 over f32 E (contiguous, 4-stage, 1 row/thread) =================
#define CHR 128
#define CBR (CHR * 64)
__global__ void __launch_bounds__(BLOCK, 6) k_gl(
    int Nj, int Nm,
    const float* __restrict__ ajWr, const float* __restrict__ ajV,
    const float* __restrict__ ajWq, const float* __restrict__ ajbq,
    const float* __restrict__ amWr, const float* __restrict__ amV,
    const float* __restrict__ amWq, const float* __restrict__ ambq,
    const float* __restrict__ g2W, const float* __restrict__ g2b)
{
    __shared__ __align__(128) char inb[4][CBR];
    __shared__ u64 mbs[4];
    __shared__ ulonglong2 sWr[64];
    __shared__ float sV[16], sQ[16];

    int t = threadIdx.x;
    int side = blockIdx.x >= BJG;
    int lb = side ? blockIdx.x - BJG : blockIdx.x;
    int nb = side ? NBMG : BJG;
    const float* X = side ? g_Em : g_Ej;
    int N = side ? Nm : Nj;
    float* part = (side ? g_pM : g_pJ) + lb * 17;
    const float* Wr = side ? amWr : ajWr; const float* V = side ? amV : ajV;
    const float* Wq = side ? amWq : ajWq; const float* bq = side ? ambq : ajbq;

    if (t < 64) sWr[t] = ((const ulonglong2*)Wr)[t];
    if (t < 16) {
        sV[t] = V[t];
        float q = bq[t];
#pragma unroll
        for (int d = 0; d < 16; d++) q += g_ejs[d] * Wq[t * 16 + d];
        sQ[t] = q;
    }
    if (t == 0) {
#pragma unroll
        for (int s = 0; s < 4; s++) mb_init(s2u(&mbs[s]), 1);
    }
    __syncthreads();

    int nch = (N + CHR - 1) / CHR;
    int c0 = (int)(((long long)lb * nch) / nb);
    int cend = (int)(((long long)(lb + 1) * nch) / nb);
    int myn = cend - c0;

    if (t == 0) {
#pragma unroll
        for (int s = 0; s < 4; s++) {
            if (s < myn) {
                int c = c0 + s;
                int rows = N - c * CHR; if (rows > CHR) rows = CHR;
                mb_tx(s2u(&mbs[s]), rows * 64);
                bulk_g2s(s2u(&inb[s][0]), (const void*)(X + (size_t)c * CHR * 16), rows * 64, s2u(&mbs[s]));
            }
        }
    }

    float S = 0.f; u64 Wa[8];
#pragma unroll
    for (int k = 0; k < 8; k++) Wa[k] = 0ull;

    for (int k = 0; k < myn; k++) {
        int c = c0 + k;
        int s = k & 3; unsigned ph = (unsigned)((k >> 2) & 1);
        mb_wait(s2u(&mbs[s]), ph);

        int row0 = c * CHR;
        int rows = N - row0; if (rows > CHR) rows = CHR;
        if (t < rows) {
            u64 x[8];
            lds_row(s2u(&inb[s][0]), t, x);
            float l = 0.f;
#pragma unroll
            for (int j = 0; j < 16; j++) {
                u64 a = 0ull;
#pragma unroll
                for (int dd = 0; dd < 4; dd++) { ulonglong2 w = sWr[j * 4 + dd]; a = F2(x[2 * dd], w.x, a); a = F2(x[2 * dd + 1], w.y, a); }
                float2 u = unpack2(a); l += sV[j] * ftanh(u.x + u.y + sQ[j]);
            }
            float w = __expf(l); S += w;
            u64 wp = pack2(w, w);
#pragma unroll
            for (int kk = 0; kk < 8; kk++) Wa[kk] = F2(wp, x[kk], Wa[kk]);
        }
        __syncthreads();
        if (t == 0) {
            int kn = k + 4;
            if (kn < myn) {
                int cn = c0 + kn;
                int rn = N - cn * CHR; if (rn > CHR) rn = CHR;
                mb_tx(s2u(&mbs[s]), rn * 64);
                bulk_g2s(s2u(&inb[s][0]), (const void*)(X + (size_t)cn * CHR * 16), rn * 64, s2u(&mbs[s]));
            }
        }
    }

    float acc[17]; acc[0] = S;
#pragma unroll
    for (int k = 0; k < 8; k++) { float2 u = unpack2(Wa[k]); acc[1 + 2 * k] = u.x; acc[2 + 2 * k] = u.y; }
    redu17(acc, part);
    __syncthreads();
    __shared__ int lastb;
    if (t == 0) { __threadfence(); lastb = (atomicAdd(&g_c2, 1) == NBG - 1); }
    __syncthreads();
    if (lastb) fin_g(t, &inb[0][0], g_ejs, g2W, g2b, g_g2, &g_c2);
}

// ================= passes 2 & 4: pointer logits (contiguous, 4-stage, 1 row/thread) =================
__global__ void __launch_bounds__(BLOCK, 6) k_arg(
    int which, int N,
    const float* __restrict__ Wr, const float* __restrict__ V,
    const float* __restrict__ Wq, const float* __restrict__ bq,
    const void* __restrict__ maskp, int nmask, float* __restrict__ out)
{
    __shared__ __align__(128) char inb[4][CBR];
    __shared__ u64 mbs[4];
    __shared__ ulonglong2 sWr[64];
    __shared__ float sV[16], sQ[16];
    __shared__ int smk;

    int t = threadIdx.x;
    const float* X = which ? g_Em : g_Ej;
    const float* qs = which ? g_g2 : g_g1;
    int* cnt = which ? &g_c3 : &g_c1;

    if (t == 0) smk = 0;
    if (t < 64) sWr[t] = ((const ulonglong2*)Wr)[t];
    if (t < 16) {
        sV[t] = V[t];
        float q = bq[t];
#pragma unroll
        for (int d = 0; d < 16; d++) q += qs[d] * Wq[t * 16 + d];
        sQ[t] = q;
    }
    if (t == 0) {
#pragma unroll
        for (int s = 0; s < 4; s++) mb_init(s2u(&mbs[s]), 1);
    }
    __syncthreads();
    // mask dtype detect: 0 = 4-byte elems, 1 = byte bools
    if (maskp) {
        int words = nmask >> 2; if (words > 4096) words = 4096;
        int f = 0;
        for (int i = t; i < words; i += BLOCK) {
            unsigned w = ((const unsigned*)maskp)[i];
            if (w != 0u && w != 1u && w != 0x3F800000u) f = 1;
        }
        if (f) atomicOr(&smk, 1);
    }
    __syncthreads();
    int mk = smk;

    int nch = (N + CHR - 1) / CHR;
    int c0 = (int)(((long long)blockIdx.x * nch) / NBG);
    int cend = (int)(((long long)(blockIdx.x + 1) * nch) / NBG);
    int myn = cend - c0;

    if (t == 0) {
#pragma unroll
        for (int s = 0; s < 4; s++) {
            if (s < myn) {
                int c = c0 + s;
                int rows = N - c * CHR; if (rows > CHR) rows = CHR;
                mb_tx(s2u(&mbs[s]), rows * 64);
                bulk_g2s(s2u(&inb[s][0]), (const void*)(X + (size_t)c * CHR * 16), rows * 64, s2u(&mbs[s]));
            }
        }
    }

    float best = -3e38f, sum = 0.f; int bi = 0x7fffffff;
    for (int k = 0; k < myn; k++) {
        int c = c0 + k;
        int s = k & 3; unsigned ph = (unsigned)((k >> 2) & 1);
        mb_wait(s2u(&mbs[s]), ph);

        int row0 = c * CHR;
        int rows = N - row0; if (rows > CHR) rows = CHR;
        if (t < rows) {
            u64 x[8];
            lds_row(s2u(&inb[s][0]), t, x);
            float l = 0.f;
#pragma unroll
            for (int j = 0; j < 16; j++) {
                u64 a = 0ull;
#pragma unroll
                for (int dd = 0; dd < 4; dd++) { ulonglong2 w = sWr[j * 4 + dd]; a = F2(x[2 * dd], w.x, a); a = F2(x[2 * dd + 1], w.y, a); }
                float2 u = unpack2(a); l += sV[j] * ftanh(u.x + u.y + sQ[j]);
            }
            int row = row0 + t;
            bool pass = true;
            if (maskp) {
                if (mk) pass = ((const unsigned char*)maskp)[row] != 0;
                else    pass = ((const unsigned*)maskp)[row] != 0u;
            }
            if (pass) {
                sum += __expf(l);
                if (l > best) { best = l; bi = row; }
            }
        }
        __syncthreads();
        if (t == 0) {
            int kn = k + 4;
            if (kn < myn) {
                int cn = c0 + kn;
                int rn = N - cn * CHR; if (rn > CHR) rn = CHR;
                mb_tx(s2u(&mbs[s]), rn * 64);
                bulk_g2s(s2u(&inb[s][0]), (const void*)(X + (size_t)cn * CHR * 16), rn * 64, s2u(&mbs[s]));
            }
        }
    }
#pragma unroll
    for (int of = 16; of > 0; of >>= 1) {
        float ov = __shfl_down_sync(0xffffffffu, best, of);
        int   oi = __shfl_down_sync(0xffffffffu, bi, of);
        sum += __shfl_down_sync(0xffffffffu, sum, of);
        if (ov > best || (ov == best && oi < bi)) { best = ov; bi = oi; }
    }
    __shared__ float wv[4], ws[4]; __shared__ int wi[4];
    int lane = t & 31, wid = t >> 5;
    if (lane == 0) { wv[wid] = best; wi[wid] = bi; ws[wid] = sum; }
    __syncthreads();
    if (t == 0) {
        float v = wv[0]; int ix = wi[0]; float s = ws[0];
#pragma unroll
        for (int w = 1; w < 4; w++) {
            if (wv[w] > v || (wv[w] == v && wi[w] < ix)) { v = wv[w]; ix = wi[w]; }
            s += ws[w];
        }
        g_aV[blockIdx.x] = v; g_aI[blockIdx.x] = ix; g_aS[blockIdx.x] = s;
    }
    __syncthreads();
    __shared__ int lastb;
    if (t == 0) { __threadfence(); lastb = (atomicAdd(cnt, 1) == NBG - 1); }
    __syncthreads();
    if (lastb) fin_arg(t, which, out, cnt);
}

extern "C" void kernel_launch(void* const* d_in, const int* in_sizes, int n_in,
                              void* d_out, int out_size) {
    const float* jobs  = (const float*)d_in[0];
    const float* machs = (const float*)d_in[1];
    const void*  mask  = d_in[2];
    const float *jW1=(const float*)d_in[3], *jb1=(const float*)d_in[4], *jW2=(const float*)d_in[5], *jb2=(const float*)d_in[6];
    const float *mW1=(const float*)d_in[7], *mb1=(const float*)d_in[8], *mW2=(const float*)d_in[9], *mb2=(const float*)d_in[10];
    const float *ajWq=(const float*)d_in[11], *ajbq=(const float*)d_in[12], *ajWr=(const float*)d_in[13], *ajV=(const float*)d_in[14];
    const float *amWq=(const float*)d_in[15], *ambq=(const float*)d_in[16], *amWr=(const float*)d_in[17], *amV=(const float*)d_in[18];
    const float *jaWq=(const float*)d_in[19], *jabq=(const float*)d_in[20], *jaWr=(const float*)d_in[21], *jaV=(const float*)d_in[22];
    const float *maWq=(const float*)d_in[23], *mabq=(const float*)d_in[24], *maWr=(const float*)d_in[25], *maV=(const float*)d_in[26];
    const float *g1W=(const float*)d_in[27], *g1b=(const float*)d_in[28];
    const float *g2W=(const float*)d_in[29], *g2b=(const float*)d_in[30];
    const float *lastj=(const float*)d_in[31];
    int Nj = in_sizes[0] / 16;
    int Nm = in_sizes[1] / 16;
    float* out = (float*)d_out;

    k_emb<<<NBG, BLOCK>>>(jobs, machs, Nj, Nm, jW1, jb1, jW2, jb2, mW1, mb1, mW2, mb2,
                          ajWr, ajV, ajWq, ajbq, amWr, amV, amWq, ambq, lastj, g1W, g1b);
    k_arg<<<NBG, BLOCK>>>(0, Nj, jaWr, jaV, jaWq, jabq, mask, in_sizes[2], out);
    k_gl <<<NBG, BLOCK>>>(Nj, Nm, ajWr, ajV, ajWq, ajbq, amWr, amV, amWq, ambq, g2W, g2b);
    k_arg<<<NBG, BLOCK>>>(1, Nm, maWr, maV, maWq, mabq, nullptr, 0, out);
    (void)n_in; (void)out_size;
}

// round 10
// speedup vs baseline: 1.2783x; 1.0280x over previous
#include <cuda_runtime.h>
#include <math.h>

#define BLOCK 128
#define NBG 888
#define BJG 592
#define NBMG (NBG - BJG)
#define IMAXX 0x7fffffff
typedef unsigned long long u64;

__device__ float g_Ej[16000000];
__device__ float g_Em[8000000];
__device__ float g_pJ[BJG * 17], g_pM[NBMG * 17];
__device__ float g_aV[NBG]; __device__ int g_aI[NBG]; __device__ float g_aS[NBG];
__device__ float g_g1[16], g_g2[16], g_ejs[16];
__device__ float g_logpj; __device__ int g_selj;
__device__ int g_c0, g_c1, g_c2, g_c3;
__device__ int g_s0, g_s1, g_s2, g_s3, g_s4, g_s5;   // steal counters

// ---------- packed f32x2 + fast math ----------
__device__ __forceinline__ u64 F2(u64 a, u64 b, u64 c) {
    u64 r; asm("fma.rn.f32x2 %0,%1,%2,%3;" : "=l"(r) : "l"(a), "l"(b), "l"(c)); return r;
}
__device__ __forceinline__ u64 pack2(float lo, float hi) {
    u64 r; asm("mov.b64 %0,{%1,%2};" : "=l"(r) : "f"(lo), "f"(hi)); return r;
}
__device__ __forceinline__ float2 unpack2(u64 v) {
    float2 r; asm("mov.b64 {%0,%1},%2;" : "=f"(r.x), "=f"(r.y) : "l"(v)); return r;
}
__device__ __forceinline__ float ftanh(float x) {
    float r; asm("tanh.approx.f32 %0,%1;" : "=f"(r) : "f"(x)); return r;
}

// ---------- bulk-async + mbarrier ----------
__device__ __forceinline__ unsigned s2u(const void* p) { return (unsigned)__cvta_generic_to_shared(p); }
__device__ __forceinline__ void mb_init(unsigned a, unsigned c) {
    asm volatile("mbarrier.init.shared.b64 [%0], %1;" :: "r"(a), "r"(c) : "memory");
}
__device__ __forceinline__ void mb_tx(unsigned a, unsigned bytes) {
    asm volatile("mbarrier.arrive.expect_tx.shared.b64 _, [%0], %1;" :: "r"(a), "r"(bytes) : "memory");
}
__device__ __forceinline__ void mb_wait(unsigned a, unsigned p) {
    asm volatile(
        "{\n\t.reg .pred P;\n"
        "WL%=:\n\t"
        "mbarrier.try_wait.parity.acquire.cta.shared::cta.b64 P, [%0], %1, 0x989680;\n\t"
        "@P bra WD%=;\n\t"
        "bra WL%=;\n"
        "WD%=:\n\t}"
        :: "r"(a), "r"(p) : "memory");
}
__device__ __forceinline__ void bulk_g2s(unsigned dst, const void* src, unsigned sz, unsigned mb) {
    asm volatile("cp.async.bulk.shared::cluster.global.mbarrier::complete_tx::bytes [%0], [%1], %2, [%3];"
                 :: "r"(dst), "l"(src), "r"(sz), "r"(mb) : "memory");
}
__device__ __forceinline__ void bulk_s2g(void* dst, unsigned src, unsigned sz) {
    asm volatile("cp.async.bulk.global.shared::cta.bulk_group [%0], [%1], %2;"
                 :: "l"(dst), "r"(src), "r"(sz) : "memory");
}
__device__ __forceinline__ void bulk_commit() { asm volatile("cp.async.bulk.commit_group;" ::: "memory"); }
__device__ __forceinline__ void bulk_wait1() { asm volatile("cp.async.bulk.wait_group 1;" ::: "memory"); }
__device__ __forceinline__ void bulk_wait0() { asm volatile("cp.async.bulk.wait_group 0;" ::: "memory"); }
__device__ __forceinline__ void fence_async() { asm volatile("fence.proxy.async.shared::cta;" ::: "memory"); }

// rotated-quarter 64B row LDS/STS
__device__ __forceinline__ void lds_row(unsigned sbase, int lr, u64 (&x)[8]) {
#pragma unroll
    for (int i = 0; i < 4; i++) {
        int q = (i + lr) & 3; u64 a, b;
        asm volatile("ld.shared.v2.b64 {%0,%1},[%2];" : "=l"(a), "=l"(b) : "r"(sbase + lr * 64 + q * 16));
        x[2 * q] = a; x[2 * q + 1] = b;
    }
}
__device__ __forceinline__ void sts_row(unsigned sbase, int lr, const u64 (&x)[8]) {
#pragma unroll
    for (int i = 0; i < 4; i++) {
        int q = (i + lr) & 3;
        asm volatile("st.shared.v2.b64 [%0],{%1,%2};" :: "r"(sbase + lr * 64 + q * 16),
                     "l"(x[2 * q]), "l"(x[2 * q + 1]) : "memory");
    }
}

__device__ __forceinline__ void redu17(float (&acc)[17], float* __restrict__ dst) {
#pragma unroll
    for (int k = 0; k < 17; k++)
#pragma unroll
        for (int o = 16; o > 0; o >>= 1) acc[k] += __shfl_down_sync(0xffffffffu, acc[k], o);
    __shared__ float red[4][17];
    int lane = threadIdx.x & 31, wid = threadIdx.x >> 5;
    if (lane == 0) {
#pragma unroll
        for (int k = 0; k < 17; k++) red[wid][k] = acc[k];
    }
    __syncthreads();
    if (threadIdx.x < 17) {
        float s = 0.f;
#pragma unroll
        for (int w = 0; w < 4; w++) s += red[w][threadIdx.x];
        dst[threadIdx.x] = s;
    }
}

// glimpse finalize (last block); scratch overlaid on dead input smem
struct FinGS { float tA[7][17]; float tB[7][17]; float sA[17]; float sB[17]; float cat[48]; float sGW[768]; };
__device__ void fin_g(int t, char* scr, const float* __restrict__ q0,
                      const float* __restrict__ gW, const float* __restrict__ gb,
                      float* __restrict__ dst, int* cnt) {
    FinGS* S = (FinGS*)scr;
    int col = t % 17, grp = t / 17;
    __syncthreads();
    if (grp < 7) {
        float a = 0.f, b = 0.f;
        for (int i = grp; i < BJG;  i += 7) a += g_pJ[i * 17 + col];
        for (int i = grp; i < NBMG; i += 7) b += g_pM[i * 17 + col];
        S->tA[grp][col] = a; S->tB[grp][col] = b;
    }
    for (int i = t; i < 768; i += BLOCK) S->sGW[i] = gW[i];
    __syncthreads();
    if (t < 17) {
        float a = 0.f, b = 0.f;
#pragma unroll
        for (int g = 0; g < 7; g++) { a += S->tA[g][t]; b += S->tB[g][t]; }
        S->sA[t] = a; S->sB[t] = b;
    }
    __syncthreads();
    if (t < 16) {
        S->cat[t] = q0[t];
        S->cat[16 + t] = S->sA[1 + t] / S->sA[0];
        S->cat[32 + t] = S->sB[1 + t] / S->sB[0];
    }
    __syncthreads();
    if (t < 16) {
        float g = gb[t];
#pragma unroll
        for (int d = 0; d < 48; d++) g += S->cat[d] * S->sGW[t * 48 + d];
        dst[t] = tanhf(g);
    }
    if (t == 0) *cnt = 0;
}

__device__ void fin_arg(int t, int which, float* __restrict__ out, int* cnt) {
    float bv = -3e38f, s = 0.f; int bi = IMAXX;
    for (int i = t; i < NBG; i += BLOCK) {
        float v = g_aV[i]; int ix = g_aI[i];
        if (v > bv || (v == bv && ix < bi)) { bv = v; bi = ix; }
        s += g_aS[i];
    }
#pragma unroll
    for (int o = 16; o > 0; o >>= 1) {
        float ov = __shfl_down_sync(0xffffffffu, bv, o);
        int   oi = __shfl_down_sync(0xffffffffu, bi, o);
        s += __shfl_down_sync(0xffffffffu, s, o);
        if (ov > bv || (ov == bv && oi < bi)) { bv = ov; bi = oi; }
    }
    __shared__ float wv[4], ws[4]; __shared__ int wi[4]; __shared__ int ssel;
    int lane = t & 31, wid = t >> 5;
    if (lane == 0) { wv[wid] = bv; wi[wid] = bi; ws[wid] = s; }
    __syncthreads();
    if (t == 0) {
        float v = wv[0]; int ix = wi[0]; float ss = ws[0];
#pragma unroll
        for (int w = 1; w < 4; w++) {
            if (wv[w] > v || (wv[w] == v && wi[w] < ix)) { v = wv[w]; ix = wi[w]; }
            ss += ws[w];
        }
        if (ix == IMAXX) ix = 0;
        if (which == 0) { g_selj = ix; g_logpj = v - logf(ss); ssel = ix; }
        else { out[0] = (float)g_selj; out[1] = (float)ix; out[2] = g_logpj + (v - logf(ss)); }
        *cnt = 0;
    }
    __syncthreads();
    if (which == 0 && t < 16) g_ejs[t] = g_Ej[ssel * 16 + t];
}

// ================= pass 1: embed + glimpse-1 (work-stealing, 2-in/2-out) =================
#define CHE 128
#define CBE (CHE * 64)
__global__ void __launch_bounds__(BLOCK, 6) k_emb(
    const float* __restrict__ jobs, const float* __restrict__ machs, int Nj, int Nm,
    const float* __restrict__ jW1, const float* __restrict__ jb1,
    const float* __restrict__ jW2, const float* __restrict__ jb2,
    const float* __restrict__ mW1, const float* __restrict__ mb1,
    const float* __restrict__ mW2, const float* __restrict__ mb2,
    const float* __restrict__ ajWr, const float* __restrict__ ajV,
    const float* __restrict__ ajWq, const float* __restrict__ ajbq,
    const float* __restrict__ amWr, const float* __restrict__ amV,
    const float* __restrict__ amWq, const float* __restrict__ ambq,
    const float* __restrict__ lastj, const float* __restrict__ g1W, const float* __restrict__ g1b)
{
    __shared__ __align__(128) char inb[2][CBE];
    __shared__ __align__(128) char outb[2][CBE];
    __shared__ u64 mbs[2];
    __shared__ int sq[2];
    __shared__ ulonglong2 sW1[64], sW2[64], sWr[64];
    __shared__ float sb1[16], sb2[16], sV[16], sQ[16];

    int t = threadIdx.x;
    int side = blockIdx.x >= BJG;
    int lb = side ? blockIdx.x - BJG : blockIdx.x;
    const float* X = side ? machs : jobs;
    int N = side ? Nm : Nj;
    float* Eo = side ? g_Em : g_Ej;
    float* part = (side ? g_pM : g_pJ) + lb * 17;
    int* sctr = side ? &g_s1 : &g_s0;
    const float* W1 = side ? mW1 : jW1; const float* b1 = side ? mb1 : jb1;
    const float* W2 = side ? mW2 : jW2; const float* b2 = side ? mb2 : jb2;
    const float* Wr = side ? amWr : ajWr; const float* V = side ? amV : ajV;
    const float* Wq = side ? amWq : ajWq; const float* bq = side ? ambq : ajbq;

    if (t < 64) {
        sW1[t] = ((const ulonglong2*)W1)[t];
        sW2[t] = ((const ulonglong2*)W2)[t];
        sWr[t] = ((const ulonglong2*)Wr)[t];
    }
    if (t < 16) {
        sb1[t] = b1[t]; sb2[t] = b2[t]; sV[t] = V[t];
        float q = bq[t];
#pragma unroll
        for (int d = 0; d < 16; d++) q += lastj[d] * Wq[t * 16 + d];
        sQ[t] = q;
    }
    if (t == 0) { mb_init(s2u(&mbs[0]), 1); mb_init(s2u(&mbs[1]), 1); }
    __syncthreads();

    int nch = (N + CHE - 1) / CHE;
    if (t == 0) {
#pragma unroll
        for (int s = 0; s < 2; s++) {
            int c = atomicAdd(sctr, 1);
            sq[s] = (c < nch) ? c : IMAXX;
            if (c < nch) {
                int rows = N - c * CHE; if (rows > CHE) rows = CHE;
                mb_tx(s2u(&mbs[s]), rows * 64);
                bulk_g2s(s2u(&inb[s][0]), (const void*)(X + (size_t)c * CHE * 16), rows * 64, s2u(&mbs[s]));
            }
        }
    }
    __syncthreads();

    float S = 0.f; u64 Wa[8];
#pragma unroll
    for (int k = 0; k < 8; k++) Wa[k] = 0ull;

    for (int k = 0; ; k++) {
        int s = k & 1;
        int c = sq[s];
        if (c == IMAXX) break;
        unsigned ph = (unsigned)((k >> 1) & 1);
        mb_wait(s2u(&mbs[s]), ph);

        int row0 = c * CHE;
        int rows = N - row0; if (rows > CHE) rows = CHE;
        bool ok = t < rows;
        u64 x[8], y[8];
        if (ok) lds_row(s2u(&inb[s][0]), t, x);
        else { for (int i = 0; i < 8; i++) x[i] = 0ull; }

        {   // layer 1
            float tp = 0.f;
#pragma unroll
            for (int j = 0; j < 16; j++) {
                u64 a = 0ull;
#pragma unroll
                for (int dd = 0; dd < 4; dd++) { ulonglong2 w = sW1[j * 4 + dd]; a = F2(x[2 * dd], w.x, a); a = F2(x[2 * dd + 1], w.y, a); }
                float2 u = unpack2(a); float tt = ftanh(u.x + u.y + sb1[j]);
                if (j & 1) y[j >> 1] = pack2(tp, tt); else tp = tt;
            }
        }
        {   // layer 2 -> embedding
            float tp = 0.f;
#pragma unroll
            for (int j = 0; j < 16; j++) {
                u64 a = 0ull;
#pragma unroll
                for (int dd = 0; dd < 4; dd++) { ulonglong2 w = sW2[j * 4 + dd]; a = F2(y[2 * dd], w.x, a); a = F2(y[2 * dd + 1], w.y, a); }
                float2 u = unpack2(a); float tt = ftanh(u.x + u.y + sb2[j]);
                if (j & 1) x[j >> 1] = pack2(tp, tt); else tp = tt;
            }
        }
        int os = k & 1;
        if (k >= 2 && t == 0) bulk_wait1();
        __syncthreads();
        if (ok) sts_row(s2u(&outb[os][0]), t, x);
        fence_async();
        if (ok) {   // glimpse-1
            float l = 0.f;
#pragma unroll
            for (int j = 0; j < 16; j++) {
                u64 a = 0ull;
#pragma unroll
                for (int dd = 0; dd < 4; dd++) { ulonglong2 w = sWr[j * 4 + dd]; a = F2(x[2 * dd], w.x, a); a = F2(x[2 * dd + 1], w.y, a); }
                float2 u = unpack2(a); l += sV[j] * ftanh(u.x + u.y + sQ[j]);
            }
            float w = __expf(l); S += w;
            u64 wp = pack2(w, w);
#pragma unroll
            for (int kk = 0; kk < 8; kk++) Wa[kk] = F2(wp, x[kk], Wa[kk]);
        }
        __syncthreads();
        if (t == 0) {
            bulk_s2g((void*)(Eo + (size_t)row0 * 16), s2u(&outb[os][0]), rows * 64);
            bulk_commit();
            int cn = atomicAdd(sctr, 1);
            sq[s] = (cn < nch) ? cn : IMAXX;
            if (cn < nch) {
                int rn = N - cn * CHE; if (rn > CHE) rn = CHE;
                mb_tx(s2u(&mbs[s]), rn * 64);
                bulk_g2s(s2u(&inb[s][0]), (const void*)(X + (size_t)cn * CHE * 16), rn * 64, s2u(&mbs[s]));
            }
        }
    }
    if (t == 0) bulk_wait0();

    float acc[17]; acc[0] = S;
#pragma unroll
    for (int k = 0; k < 8; k++) { float2 u = unpack2(Wa[k]); acc[1 + 2 * k] = u.x; acc[2 + 2 * k] = u.y; }
    redu17(acc, part);
    __syncthreads();
    __shared__ int lastb;
    if (t == 0) { __threadfence(); lastb = (atomicAdd(&g_c0, 1) == NBG - 1); }
    __syncthreads();
    if (lastb) {
        fin_g(t, &inb[0][0], lastj, g1W, g1b, g_g1, &g_c0);
        if (t == 0) { g_s0 = 0; g_s1 = 0; }
    }
}

// ================= pass 3: glimpse-2 (work-stealing, 4-stage, 1 row/thread) =================
#define CHR 128
#define CBR (CHR * 64)
__global__ void __launch_bounds__(BLOCK, 6) k_gl(
    int Nj, int Nm,
    const float* __restrict__ ajWr, const float* __restrict__ ajV,
    const float* __restrict__ ajWq, const float* __restrict__ ajbq,
    const float* __restrict__ amWr, const float* __restrict__ amV,
    const float* __restrict__ amWq, const float* __restrict__ ambq,
    const float* __restrict__ g2W, const float* __restrict__ g2b)
{
    __shared__ __align__(128) char inb[4][CBR];
    __shared__ u64 mbs[4];
    __shared__ int sq[4];
    __shared__ ulonglong2 sWr[64];
    __shared__ float sV[16], sQ[16];

    int t = threadIdx.x;
    int side = blockIdx.x >= BJG;
    int lb = side ? blockIdx.x - BJG : blockIdx.x;
    const float* X = side ? g_Em : g_Ej;
    int N = side ? Nm : Nj;
    float* part = (side ? g_pM : g_pJ) + lb * 17;
    int* sctr = side ? &g_s4 : &g_s3;
    const float* Wr = side ? amWr : ajWr; const float* V = side ? amV : ajV;
    const float* Wq = side ? amWq : ajWq; const float* bq = side ? ambq : ajbq;

    if (t < 64) sWr[t] = ((const ulonglong2*)Wr)[t];
    if (t < 16) {
        sV[t] = V[t];
        float q = bq[t];
#pragma unroll
        for (int d = 0; d < 16; d++) q += g_ejs[d] * Wq[t * 16 + d];
        sQ[t] = q;
    }
    if (t == 0) {
#pragma unroll
        for (int s = 0; s < 4; s++) mb_init(s2u(&mbs[s]), 1);
    }
    __syncthreads();

    int nch = (N + CHR - 1) / CHR;
    if (t == 0) {
#pragma unroll
        for (int s = 0; s < 4; s++) {
            int c = atomicAdd(sctr, 1);
            sq[s] = (c < nch) ? c : IMAXX;
            if (c < nch) {
                int rows = N - c * CHR; if (rows > CHR) rows = CHR;
                mb_tx(s2u(&mbs[s]), rows * 64);
                bulk_g2s(s2u(&inb[s][0]), (const void*)(X + (size_t)c * CHR * 16), rows * 64, s2u(&mbs[s]));
            }
        }
    }
    __syncthreads();

    float S = 0.f; u64 Wa[8];
#pragma unroll
    for (int k = 0; k < 8; k++) Wa[k] = 0ull;

    for (int k = 0; ; k++) {
        int s = k & 3;
        int c = sq[s];
        if (c == IMAXX) break;
        unsigned ph = (unsigned)((k >> 2) & 1);
        mb_wait(s2u(&mbs[s]), ph);

        int row0 = c * CHR;
        int rows = N - row0; if (rows > CHR) rows = CHR;
        if (t < rows) {
            u64 x[8];
            lds_row(s2u(&inb[s][0]), t, x);
            float l = 0.f;
#pragma unroll
            for (int j = 0; j < 16; j++) {
                u64 a = 0ull;
#pragma unroll
                for (int dd = 0; dd < 4; dd++) { ulonglong2 w = sWr[j * 4 + dd]; a = F2(x[2 * dd], w.x, a); a = F2(x[2 * dd + 1], w.y, a); }
                float2 u = unpack2(a); l += sV[j] * ftanh(u.x + u.y + sQ[j]);
            }
            float w = __expf(l); S += w;
            u64 wp = pack2(w, w);
#pragma unroll
            for (int kk = 0; kk < 8; kk++) Wa[kk] = F2(wp, x[kk], Wa[kk]);
        }
        __syncthreads();
        if (t == 0) {
            int cn = atomicAdd(sctr, 1);
            sq[s] = (cn < nch) ? cn : IMAXX;
            if (cn < nch) {
                int rn = N - cn * CHR; if (rn > CHR) rn = CHR;
                mb_tx(s2u(&mbs[s]), rn * 64);
                bulk_g2s(s2u(&inb[s][0]), (const void*)(X + (size_t)cn * CHR * 16), rn * 64, s2u(&mbs[s]));
            }
        }
    }

    float acc[17]; acc[0] = S;
#pragma unroll
    for (int k = 0; k < 8; k++) { float2 u = unpack2(Wa[k]); acc[1 + 2 * k] = u.x; acc[2 + 2 * k] = u.y; }
    redu17(acc, part);
    __syncthreads();
    __shared__ int lastb;
    if (t == 0) { __threadfence(); lastb = (atomicAdd(&g_c2, 1) == NBG - 1); }
    __syncthreads();
    if (lastb) {
        fin_g(t, &inb[0][0], g_ejs, g2W, g2b, g_g2, &g_c2);
        if (t == 0) { g_s3 = 0; g_s4 = 0; }
    }
}

// ================= passes 2 & 4: pointer logits (work-stealing, 4-stage) =================
__global__ void __launch_bounds__(BLOCK, 6) k_arg(
    int which, int N,
    const float* __restrict__ Wr, const float* __restrict__ V,
    const float* __restrict__ Wq, const float* __restrict__ bq,
    const void* __restrict__ maskp, int nmask, float* __restrict__ out)
{
    __shared__ __align__(128) char inb[4][CBR];
    __shared__ u64 mbs[4];
    __shared__ int sq[4];
    __shared__ ulonglong2 sWr[64];
    __shared__ float sV[16], sQ[16];
    __shared__ int smk;

    int t = threadIdx.x;
    const float* X = which ? g_Em : g_Ej;
    const float* qs = which ? g_g2 : g_g1;
    int* cnt = which ? &g_c3 : &g_c1;
    int* sctr = which ? &g_s5 : &g_s2;

    if (t == 0) smk = 0;
    if (t < 64) sWr[t] = ((const ulonglong2*)Wr)[t];
    if (t < 16) {
        sV[t] = V[t];
        float q = bq[t];
#pragma unroll
        for (int d = 0; d < 16; d++) q += qs[d] * Wq[t * 16 + d];
        sQ[t] = q;
    }
    if (t == 0) {
#pragma unroll
        for (int s = 0; s < 4; s++) mb_init(s2u(&mbs[s]), 1);
    }
    __syncthreads();
    // mask dtype detect: 0 = 4-byte elems, 1 = byte bools
    if (maskp) {
        int words = nmask >> 2; if (words > 4096) words = 4096;
        int f = 0;
        for (int i = t; i < words; i += BLOCK) {
            unsigned w = ((const unsigned*)maskp)[i];
            if (w != 0u && w != 1u && w != 0x3F800000u) f = 1;
        }
        if (f) atomicOr(&smk, 1);
    }
    __syncthreads();
    int mk = smk;

    int nch = (N + CHR - 1) / CHR;
    if (t == 0) {
#pragma unroll
        for (int s = 0; s < 4; s++) {
            int c = atomicAdd(sctr, 1);
            sq[s] = (c < nch) ? c : IMAXX;
            if (c < nch) {
                int rows = N - c * CHR; if (rows > CHR) rows = CHR;
                mb_tx(s2u(&mbs[s]), rows * 64);
                bulk_g2s(s2u(&inb[s][0]), (const void*)(X + (size_t)c * CHR * 16), rows * 64, s2u(&mbs[s]));
            }
        }
    }
    __syncthreads();

    float best = -3e38f, sum = 0.f; int bi = IMAXX;
    for (int k = 0; ; k++) {
        int s = k & 3;
        int c = sq[s];
        if (c == IMAXX) break;
        unsigned ph = (unsigned)((k >> 2) & 1);
        mb_wait(s2u(&mbs[s]), ph);

        int row0 = c * CHR;
        int rows = N - row0; if (rows > CHR) rows = CHR;
        if (t < rows) {
            u64 x[8];
            lds_row(s2u(&inb[s][0]), t, x);
            float l = 0.f;
#pragma unroll
            for (int j = 0; j < 16; j++) {
                u64 a = 0ull;
#pragma unroll
                for (int dd = 0; dd < 4; dd++) { ulonglong2 w = sWr[j * 4 + dd]; a = F2(x[2 * dd], w.x, a); a = F2(x[2 * dd + 1], w.y, a); }
                float2 u = unpack2(a); l += sV[j] * ftanh(u.x + u.y + sQ[j]);
            }
            int row = row0 + t;
            bool pass = true;
            if (maskp) {
                if (mk) pass = ((const unsigned char*)maskp)[row] != 0;
                else    pass = ((const unsigned*)maskp)[row] != 0u;
            }
            if (pass) {
                sum += __expf(l);
                if (l > best) { best = l; bi = row; }
            }
        }
        __syncthreads();
        if (t == 0) {
            int cn = atomicAdd(sctr, 1);
            sq[s] = (cn < nch) ? cn : IMAXX;
            if (cn < nch) {
                int rn = N - cn * CHR; if (rn > CHR) rn = CHR;
                mb_tx(s2u(&mbs[s]), rn * 64);
                bulk_g2s(s2u(&inb[s][0]), (const void*)(X + (size_t)cn * CHR * 16), rn * 64, s2u(&mbs[s]));
            }
        }
    }
#pragma unroll
    for (int of = 16; of > 0; of >>= 1) {
        float ov = __shfl_down_sync(0xffffffffu, best, of);
        int   oi = __shfl_down_sync(0xffffffffu, bi, of);
        sum += __shfl_down_sync(0xffffffffu, sum, of);
        if (ov > best || (ov == best && oi < bi)) { best = ov; bi = oi; }
    }
    __shared__ float wv[4], ws[4]; __shared__ int wi[4];
    int lane = t & 31, wid = t >> 5;
    if (lane == 0) { wv[wid] = best; wi[wid] = bi; ws[wid] = sum; }
    __syncthreads();
    if (t == 0) {
        float v = wv[0]; int ix = wi[0]; float s = ws[0];
#pragma unroll
        for (int w = 1; w < 4; w++) {
            if (wv[w] > v || (wv[w] == v && wi[w] < ix)) { v = wv[w]; ix = wi[w]; }
            s += ws[w];
        }
        g_aV[blockIdx.x] = v; g_aI[blockIdx.x] = ix; g_aS[blockIdx.x] = s;
    }
    __syncthreads();
    __shared__ int lastb;
    if (t == 0) { __threadfence(); lastb = (atomicAdd(cnt, 1) == NBG - 1); }
    __syncthreads();
    if (lastb) {
        fin_arg(t, which, out, cnt);
        if (t == 0) { if (which) g_s5 = 0; else g_s2 = 0; }
    }
}

extern "C" void kernel_launch(void* const* d_in, const int* in_sizes, int n_in,
                              void* d_out, int out_size) {
    const float* jobs  = (const float*)d_in[0];
    const float* machs = (const float*)d_in[1];
    const void*  mask  = d_in[2];
    const float *jW1=(const float*)d_in[3], *jb1=(const float*)d_in[4], *jW2=(const float*)d_in[5], *jb2=(const float*)d_in[6];
    const float *mW1=(const float*)d_in[7], *mb1=(const float*)d_in[8], *mW2=(const float*)d_in[9], *mb2=(const float*)d_in[10];
    const float *ajWq=(const float*)d_in[11], *ajbq=(const float*)d_in[12], *ajWr=(const float*)d_in[13], *ajV=(const float*)d_in[14];
    const float *amWq=(const float*)d_in[15], *ambq=(const float*)d_in[16], *amWr=(const float*)d_in[17], *amV=(const float*)d_in[18];
    const float *jaWq=(const float*)d_in[19], *jabq=(const float*)d_in[20], *jaWr=(const float*)d_in[21], *jaV=(const float*)d_in[22];
    const float *maWq=(const float*)d_in[23], *mabq=(const float*)d_in[24], *maWr=(const float*)d_in[25], *maV=(const float*)d_in[26];
    const float *g1W=(const float*)d_in[27], *g1b=(const float*)d_in[28];
    const float *g2W=(const float*)d_in[29], *g2b=(const float*)d_in[30];
    const float *lastj=(const float*)d_in[31];
    int Nj = in_sizes[0] / 16;
    int Nm = in_sizes[1] / 16;
    float* out = (float*)d_out;

    k_emb<<<NBG, BLOCK>>>(jobs, machs, Nj, Nm, jW1, jb1, jW2, jb2, mW1, mb1, mW2, mb2,
                          ajWr, ajV, ajWq, ajbq, amWr, amV, amWq, ambq, lastj, g1W, g1b);
    k_arg<<<NBG, BLOCK>>>(0, Nj, jaWr, jaV, jaWq, jabq, mask, in_sizes[2], out);
    k_gl <<<NBG, BLOCK>>>(Nj, Nm, ajWr, ajV, ajWq, ajbq, amWr, amV, amWq, ambq, g2W, g2b);
    k_arg<<<NBG, BLOCK>>>(1, Nm, maWr, maV, maWq, mabq, nullptr, 0, out);
    (void)n_in; (void)out_size;
}